// round 1
// baseline (speedup 1.0000x reference)
#include <cuda_runtime.h>
#include <math.h>

#define Bv 4
#define Nv 2048
#define Fv 256
#define Dv 128
#define Hv 4

// Scratch (device globals per harness rules; ~32 MB total)
__device__ float g_Hx0 [Bv*Nv*Dv];      // X@kernel + bias
__device__ float g_Hx  [Bv*Nv*Dv];      // A @ Hx0
__device__ float g_Xs  [Bv*Nv*Dv];      // X@W_skip + b_skip
__device__ float g_Q   [Hv*Bv*Nv*Dv];   // Hx @ attn[h]
__device__ float g_Hout[Bv*Nv*Dv];      // relu(mean_h heads)

// ---------------------------------------------------------------------------
// K1: Hx0 = X@kernel + bias   and   Xs = X@W_skip + b_skip   (shared X tiles)
// block = 64 rows x 128 cols, 256 threads, each thread 4x8 (cols = tx + 16*j)
// ---------------------------------------------------------------------------
__global__ __launch_bounds__(256) void proj_kernel(
    const float* __restrict__ X, const float* __restrict__ Wk,
    const float* __restrict__ bias, const float* __restrict__ Ws,
    const float* __restrict__ bskip)
{
    extern __shared__ float sm[];
    float* sX = sm;             // [64][68]
    float* sK = sX + 64*68;     // [64][128]
    float* sW = sK + 64*128;    // [64][128]
    const int tid = threadIdx.x, ty = tid >> 4, tx = tid & 15;
    const int row0 = blockIdx.x * 64;   // global row over B*N

    float acc1[4][8], acc2[4][8];
#pragma unroll
    for (int i = 0; i < 4; i++)
#pragma unroll
        for (int j = 0; j < 8; j++) { acc1[i][j] = 0.f; acc2[i][j] = 0.f; }

    for (int k0 = 0; k0 < Fv; k0 += 64) {
#pragma unroll
        for (int s = 0; s < 16; s++) {
            int idx = tid + 256 * s; int r = idx >> 6, c = idx & 63;
            sX[r*68 + c] = X[(size_t)(row0 + r) * Fv + k0 + c];
        }
#pragma unroll
        for (int s = 0; s < 8; s++) {
            int idx4 = tid + 256 * s; int r = idx4 >> 5, c4 = (idx4 & 31) * 4;
            *(float4*)&sK[r*128 + c4] = *(const float4*)&Wk[(size_t)(k0 + r) * Dv + c4];
            *(float4*)&sW[r*128 + c4] = *(const float4*)&Ws[(size_t)(k0 + r) * Dv + c4];
        }
        __syncthreads();
#pragma unroll 8
        for (int kk = 0; kk < 64; kk++) {
            float a[4], b1[8], b2[8];
#pragma unroll
            for (int i = 0; i < 4; i++) a[i] = sX[(ty*4 + i)*68 + kk];
#pragma unroll
            for (int j = 0; j < 8; j++) {
                b1[j] = sK[kk*128 + tx + 16*j];
                b2[j] = sW[kk*128 + tx + 16*j];
            }
#pragma unroll
            for (int i = 0; i < 4; i++)
#pragma unroll
                for (int j = 0; j < 8; j++) {
                    acc1[i][j] += a[i] * b1[j];
                    acc2[i][j] += a[i] * b2[j];
                }
        }
        __syncthreads();
    }
#pragma unroll
    for (int i = 0; i < 4; i++)
#pragma unroll
        for (int j = 0; j < 8; j++) {
            int r = row0 + ty*4 + i, c = tx + 16*j;
            g_Hx0[(size_t)r * Dv + c] = acc1[i][j] + bias[c];
            g_Xs [(size_t)r * Dv + c] = acc2[i][j] + bskip[c];
        }
}

// ---------------------------------------------------------------------------
// K2: Hx = A @ Hx0   (per batch: [2048x2048] @ [2048x128])
// grid (32, B), block 64x128, 256 threads
// ---------------------------------------------------------------------------
__global__ __launch_bounds__(256) void aggr_kernel(const float* __restrict__ A)
{
    extern __shared__ float sm[];
    float* sA = sm;             // [64][68]
    float* sH = sA + 64*68;     // [64][128]
    const int tid = threadIdx.x, ty = tid >> 4, tx = tid & 15;
    const int b = blockIdx.y, row0 = blockIdx.x * 64;
    const float* Ab = A + (size_t)b * Nv * Nv;
    const float* Hb = g_Hx0 + (size_t)b * Nv * Dv;

    float acc[4][8];
#pragma unroll
    for (int i = 0; i < 4; i++)
#pragma unroll
        for (int j = 0; j < 8; j++) acc[i][j] = 0.f;

    for (int k0 = 0; k0 < Nv; k0 += 64) {
#pragma unroll
        for (int s = 0; s < 16; s++) {
            int idx = tid + 256 * s; int r = idx >> 6, c = idx & 63;
            sA[r*68 + c] = Ab[(size_t)(row0 + r) * Nv + k0 + c];
        }
#pragma unroll
        for (int s = 0; s < 8; s++) {
            int idx4 = tid + 256 * s; int r = idx4 >> 5, c4 = (idx4 & 31) * 4;
            *(float4*)&sH[r*128 + c4] = *(const float4*)&Hb[(size_t)(k0 + r) * Dv + c4];
        }
        __syncthreads();
#pragma unroll 8
        for (int kk = 0; kk < 64; kk++) {
            float a[4], bb[8];
#pragma unroll
            for (int i = 0; i < 4; i++) a[i] = sA[(ty*4 + i)*68 + kk];
#pragma unroll
            for (int j = 0; j < 8; j++) bb[j] = sH[kk*128 + tx + 16*j];
#pragma unroll
            for (int i = 0; i < 4; i++)
#pragma unroll
                for (int j = 0; j < 8; j++) acc[i][j] += a[i] * bb[j];
        }
        __syncthreads();
    }
#pragma unroll
    for (int i = 0; i < 4; i++)
#pragma unroll
        for (int j = 0; j < 8; j++) {
            int r = row0 + ty*4 + i, c = tx + 16*j;
            g_Hx[((size_t)b * Nv + r) * Dv + c] = acc[i][j];
        }
}

// ---------------------------------------------------------------------------
// K3: Q[h,b] = Hx[b] @ attn[h]   ([2048x128] @ [128x128])
// grid (32, B, H)
// ---------------------------------------------------------------------------
__global__ __launch_bounds__(256) void q_kernel(const float* __restrict__ attn)
{
    extern __shared__ float sm[];
    float* sHx = sm;              // [64][132]
    float* sAt = sHx + 64*132;    // [128][128]
    const int tid = threadIdx.x, ty = tid >> 4, tx = tid & 15;
    const int b = blockIdx.y, h = blockIdx.z, n0 = blockIdx.x * 64;
    const float* Hb = g_Hx + (size_t)b * Nv * Dv;
    const float* At = attn + (size_t)h * Dv * Dv;

#pragma unroll
    for (int s = 0; s < 8; s++) {
        int idx4 = tid + 256 * s; int m = idx4 >> 5, e4 = (idx4 & 31) * 4;
        *(float4*)&sHx[m*132 + e4] = *(const float4*)&Hb[(size_t)(n0 + m) * Dv + e4];
    }
#pragma unroll
    for (int s = 0; s < 16; s++) {
        int idx4 = tid + 256 * s; int r = idx4 >> 5, c4 = (idx4 & 31) * 4;
        *(float4*)&sAt[r*128 + c4] = *(const float4*)&At[(size_t)r * Dv + c4];
    }
    __syncthreads();

    float acc[4][8];
#pragma unroll
    for (int i = 0; i < 4; i++)
#pragma unroll
        for (int j = 0; j < 8; j++) acc[i][j] = 0.f;

#pragma unroll 8
    for (int k = 0; k < Dv; k++) {
        float a[4], bb[8];
#pragma unroll
        for (int i = 0; i < 4; i++) a[i] = sHx[(ty*4 + i)*132 + k];
#pragma unroll
        for (int j = 0; j < 8; j++) bb[j] = sAt[k*128 + tx + 16*j];
#pragma unroll
        for (int i = 0; i < 4; i++)
#pragma unroll
            for (int j = 0; j < 8; j++) acc[i][j] += a[i] * bb[j];
    }
#pragma unroll
    for (int i = 0; i < 4; i++)
#pragma unroll
        for (int j = 0; j < 8; j++) {
            int r = n0 + ty*4 + i, c = tx + 16*j;
            g_Q[(((size_t)h * Bv + b) * Nv + r) * Dv + c] = acc[i][j];
        }
}

// ---------------------------------------------------------------------------
// K4: fused attention. grid (32, B). Per block: rows n0..n0+63.
// acc[n,d] = sum_h sum_m tanh(A[n,m] * (Q_h[n,:]·Hx[m,:])) * Hx[m,d]
// Hout = relu(acc/4)
// ---------------------------------------------------------------------------
__global__ __launch_bounds__(256) void attn_kernel(const float* __restrict__ A)
{
    extern __shared__ float sm[];
    float* sQ   = sm;               // [64][132]
    float* sHx  = sQ  + 64*132;     // [64][132]  row-major (GEMM2 B operand)
    float* sHxT = sHx + 64*132;     // [128][65]  transposed (GEMM1 B operand)
    float* sA   = sHxT + 128*65;    // [64][68]   A tile, overwritten in-place with Am
    const int tid = threadIdx.x, ty = tid >> 4, tx = tid & 15;
    const int b = blockIdx.y, n0 = blockIdx.x * 64;
    const float* Ab = A + (size_t)b * Nv * Nv;
    const float* Hb = g_Hx + (size_t)b * Nv * Dv;

    float acc[4][8];
#pragma unroll
    for (int i = 0; i < 4; i++)
#pragma unroll
        for (int j = 0; j < 8; j++) acc[i][j] = 0.f;

    for (int h = 0; h < Hv; h++) {
        const float* Qb = g_Q + ((size_t)h * Bv + b) * Nv * Dv;
#pragma unroll
        for (int s = 0; s < 8; s++) {
            int idx4 = tid + 256 * s; int r = idx4 >> 5, c4 = (idx4 & 31) * 4;
            *(float4*)&sQ[r*132 + c4] = *(const float4*)&Qb[(size_t)(n0 + r) * Dv + c4];
        }
        for (int mt = 0; mt < Nv / 64; mt++) {
            const int m0 = mt * 64;
            // Hx m-tile into both layouts
#pragma unroll
            for (int s = 0; s < 8; s++) {
                int idx4 = tid + 256 * s; int m = idx4 >> 5, e4 = (idx4 & 31) * 4;
                float4 v = *(const float4*)&Hb[(size_t)(m0 + m) * Dv + e4];
                *(float4*)&sHx[m*132 + e4] = v;
                sHxT[(e4 + 0)*65 + m] = v.x;
                sHxT[(e4 + 1)*65 + m] = v.y;
                sHxT[(e4 + 2)*65 + m] = v.z;
                sHxT[(e4 + 3)*65 + m] = v.w;
            }
            // A tile [64 n][64 m]
#pragma unroll
            for (int s = 0; s < 16; s++) {
                int idx = tid + 256 * s; int r = idx >> 6, c = idx & 63;
                sA[r*68 + c] = Ab[(size_t)(n0 + r) * Nv + m0 + c];
            }
            __syncthreads();

            // GEMM1: S[64n][64m] = Q @ Hx^T, micro 4x4 (cols = tx + 16*j)
            float S[4][4];
#pragma unroll
            for (int i = 0; i < 4; i++)
#pragma unroll
                for (int j = 0; j < 4; j++) S[i][j] = 0.f;
#pragma unroll 8
            for (int e = 0; e < Dv; e++) {
                float a[4], bv[4];
#pragma unroll
                for (int i = 0; i < 4; i++) a[i] = sQ[(ty*4 + i)*132 + e];
#pragma unroll
                for (int j = 0; j < 4; j++) bv[j] = sHxT[e*65 + tx + 16*j];
#pragma unroll
                for (int i = 0; i < 4; i++)
#pragma unroll
                    for (int j = 0; j < 4; j++) S[i][j] += a[i] * bv[j];
            }
            // Am = tanh(A * S), written in place (one-to-one element mapping)
#pragma unroll
            for (int i = 0; i < 4; i++)
#pragma unroll
                for (int j = 0; j < 4; j++) {
                    int r = ty*4 + i, c = tx + 16*j;
                    float av = sA[r*68 + c];
                    sA[r*68 + c] = tanhf(av * S[i][j]);
                }
            __syncthreads();

            // GEMM2: acc += Am[64n][64m] @ Hx[64m][128d]
#pragma unroll 8
            for (int k = 0; k < 64; k++) {
                float a[4], bv[8];
#pragma unroll
                for (int i = 0; i < 4; i++) a[i] = sA[(ty*4 + i)*68 + k];
#pragma unroll
                for (int j = 0; j < 8; j++) bv[j] = sHx[k*132 + tx + 16*j];
#pragma unroll
                for (int i = 0; i < 4; i++)
#pragma unroll
                    for (int j = 0; j < 8; j++) acc[i][j] += a[i] * bv[j];
            }
            __syncthreads();
        }
    }
    // Hout = relu(mean over heads)
#pragma unroll
    for (int i = 0; i < 4; i++)
#pragma unroll
        for (int j = 0; j < 8; j++) {
            int r = n0 + ty*4 + i, c = tx + 16*j;
            float v = acc[i][j] * 0.25f;
            g_Hout[((size_t)b * Nv + r) * Dv + c] = v > 0.f ? v : 0.f;
        }
}

// ---------------------------------------------------------------------------
// K5: z = sigmoid(Hout@W_u + Xs@W_x + b_u + b_x + update_bias)
//     out = Hout*z + Xs*(1-z)
// ---------------------------------------------------------------------------
__global__ __launch_bounds__(256) void gate_kernel(
    const float* __restrict__ Wu, const float* __restrict__ bu,
    const float* __restrict__ Wx, const float* __restrict__ bx,
    const float* __restrict__ ub, float* __restrict__ out)
{
    extern __shared__ float sm[];
    float* sHo = sm;              // [64][132]
    float* sXs = sHo + 64*132;    // [64][132]
    float* sWu = sXs + 64*132;    // [64][128]
    float* sWx = sWu + 64*128;    // [64][128]
    const int tid = threadIdx.x, ty = tid >> 4, tx = tid & 15;
    const int row0 = blockIdx.x * 64;   // global over B*N

#pragma unroll
    for (int s = 0; s < 8; s++) {
        int idx4 = tid + 256 * s; int r = idx4 >> 5, c4 = (idx4 & 31) * 4;
        *(float4*)&sHo[r*132 + c4] = *(const float4*)&g_Hout[(size_t)(row0 + r) * Dv + c4];
        *(float4*)&sXs[r*132 + c4] = *(const float4*)&g_Xs  [(size_t)(row0 + r) * Dv + c4];
    }

    float acc[4][8];
#pragma unroll
    for (int i = 0; i < 4; i++)
#pragma unroll
        for (int j = 0; j < 8; j++) acc[i][j] = 0.f;

    for (int k0 = 0; k0 < Dv; k0 += 64) {
#pragma unroll
        for (int s = 0; s < 8; s++) {
            int idx4 = tid + 256 * s; int r = idx4 >> 5, c4 = (idx4 & 31) * 4;
            *(float4*)&sWu[r*128 + c4] = *(const float4*)&Wu[(size_t)(k0 + r) * Dv + c4];
            *(float4*)&sWx[r*128 + c4] = *(const float4*)&Wx[(size_t)(k0 + r) * Dv + c4];
        }
        __syncthreads();
#pragma unroll 8
        for (int kk = 0; kk < 64; kk++) {
            float a1[4], a2[4], b1[8], b2[8];
#pragma unroll
            for (int i = 0; i < 4; i++) {
                a1[i] = sHo[(ty*4 + i)*132 + k0 + kk];
                a2[i] = sXs[(ty*4 + i)*132 + k0 + kk];
            }
#pragma unroll
            for (int j = 0; j < 8; j++) {
                b1[j] = sWu[kk*128 + tx + 16*j];
                b2[j] = sWx[kk*128 + tx + 16*j];
            }
#pragma unroll
            for (int i = 0; i < 4; i++)
#pragma unroll
                for (int j = 0; j < 8; j++)
                    acc[i][j] += a1[i] * b1[j] + a2[i] * b2[j];
        }
        __syncthreads();
    }
#pragma unroll
    for (int i = 0; i < 4; i++)
#pragma unroll
        for (int j = 0; j < 8; j++) {
            int r = ty*4 + i, c = tx + 16*j;
            float ho = sHo[r*132 + c];
            float xs = sXs[r*132 + c];
            float zl = acc[i][j] + bu[c] + bx[c] + ub[c];
            float z = 1.f / (1.f + expf(-zl));
            out[(size_t)(row0 + r) * Dv + c] = ho * z + xs * (1.f - z);
        }
}

// ---------------------------------------------------------------------------
extern "C" void kernel_launch(void* const* d_in, const int* in_sizes, int n_in,
                              void* d_out, int out_size)
{
    const float* X      = (const float*)d_in[0];
    const float* A      = (const float*)d_in[1];
    const float* Wk     = (const float*)d_in[2];
    const float* bias   = (const float*)d_in[3];
    const float* ub     = (const float*)d_in[4];
    const float* attn   = (const float*)d_in[5];
    const float* Wskip  = (const float*)d_in[6];
    const float* bskip  = (const float*)d_in[7];
    const float* Wu     = (const float*)d_in[8];
    const float* bu     = (const float*)d_in[9];
    const float* Wx     = (const float*)d_in[10];
    const float* bx     = (const float*)d_in[11];
    float* out = (float*)d_out;

    const int SM1 = (64*68 + 2*64*128) * 4;
    const int SM2 = (64*68 + 64*128) * 4;
    const int SM3 = (64*132 + 128*128) * 4;
    const int SM4 = (2*64*132 + 128*65 + 64*68) * 4;
    const int SM5 = (2*64*132 + 2*64*128) * 4;
    cudaFuncSetAttribute(proj_kernel, cudaFuncAttributeMaxDynamicSharedMemorySize, SM1);
    cudaFuncSetAttribute(aggr_kernel, cudaFuncAttributeMaxDynamicSharedMemorySize, SM2);
    cudaFuncSetAttribute(q_kernel,    cudaFuncAttributeMaxDynamicSharedMemorySize, SM3);
    cudaFuncSetAttribute(attn_kernel, cudaFuncAttributeMaxDynamicSharedMemorySize, SM4);
    cudaFuncSetAttribute(gate_kernel, cudaFuncAttributeMaxDynamicSharedMemorySize, SM5);

    proj_kernel<<<(Bv*Nv)/64, 256, SM1>>>(X, Wk, bias, Wskip, bskip);
    aggr_kernel<<<dim3(Nv/64, Bv), 256, SM2>>>(A);
    q_kernel   <<<dim3(Nv/64, Bv, Hv), 256, SM3>>>(attn);
    attn_kernel<<<dim3(Nv/64, Bv), 256, SM4>>>(A);
    gate_kernel<<<(Bv*Nv)/64, 256, SM5>>>(Wu, bu, Wx, bx, ub, out);

    // Second tuple element: copy A into the tail of the output buffer.
    cudaMemcpyAsync(out + (size_t)Bv*Nv*Dv, A,
                    (size_t)Bv*Nv*Nv * sizeof(float),
                    cudaMemcpyDeviceToDevice);
}

// round 3
// speedup vs baseline: 2.8218x; 2.8218x over previous
#include <cuda_runtime.h>
#include <math.h>
#include <stdint.h>

#define Bv 4
#define Nv 2048
#define Fv 256
#define Dv 128
#define Hv 4

// Scratch (device globals per harness rules)
__device__ float g_Hx0 [Bv*Nv*Dv];      // X@kernel + bias
__device__ float g_Hx  [Bv*Nv*Dv];      // A @ Hx0
__device__ float g_Xs  [Bv*Nv*Dv];      // X@W_skip + b_skip
__device__ float g_Q   [Hv*Bv*Nv*Dv];   // Hx @ attn[h]
__device__ float g_Hout[Bv*Nv*Dv];      // relu(mean_h heads)

// ---------------------------------------------------------------------------
// tf32 mma helpers
// ---------------------------------------------------------------------------
__device__ __forceinline__ unsigned f2tf(float f) {
    unsigned u; asm("cvt.rna.tf32.f32 %0, %1;" : "=r"(u) : "f"(f)); return u;
}
__device__ __forceinline__ float tanh_fast(float x) {
    float y; asm("tanh.approx.f32 %0, %1;" : "=f"(y) : "f"(x)); return y;
}
__device__ __forceinline__ void mma_tf32(float c[4], const unsigned a[4], const unsigned b[2]) {
    asm volatile(
        "mma.sync.aligned.m16n8k8.row.col.f32.tf32.tf32.f32 "
        "{%0,%1,%2,%3}, {%4,%5,%6,%7}, {%8,%9}, {%0,%1,%2,%3};"
        : "+f"(c[0]), "+f"(c[1]), "+f"(c[2]), "+f"(c[3])
        : "r"(a[0]), "r"(a[1]), "r"(a[2]), "r"(a[3]), "r"(b[0]), "r"(b[1]));
}
__device__ __forceinline__ unsigned ldsu(const float* p) { return __float_as_uint(*p); }

// Strides chosen for bank-conflict-free mma fragment loads:
//  SB=140 (mod 32 == 12): both (12k+n) and (12n+k) access patterns conflict-free
//  SA=68  (mod 32 == 4):  A-operand pattern (4n+k) conflict-free
#define SB 140
#define SA 68

// ---------------------------------------------------------------------------
// K1: Hx0 = X@kernel + bias   and   Xs = X@W_skip + b_skip   (SIMT, small)
// ---------------------------------------------------------------------------
__global__ __launch_bounds__(256) void proj_kernel(
    const float* __restrict__ X, const float* __restrict__ Wk,
    const float* __restrict__ bias, const float* __restrict__ Ws,
    const float* __restrict__ bskip)
{
    extern __shared__ float sm[];
    float* sX = sm;             // [64][68]
    float* sK = sX + 64*68;     // [64][128]
    float* sW = sK + 64*128;    // [64][128]
    const int tid = threadIdx.x, ty = tid >> 4, tx = tid & 15;
    const int row0 = blockIdx.x * 64;

    float acc1[4][8], acc2[4][8];
#pragma unroll
    for (int i = 0; i < 4; i++)
#pragma unroll
        for (int j = 0; j < 8; j++) { acc1[i][j] = 0.f; acc2[i][j] = 0.f; }

    for (int k0 = 0; k0 < Fv; k0 += 64) {
#pragma unroll
        for (int s = 0; s < 16; s++) {
            int idx = tid + 256 * s; int r = idx >> 6, c = idx & 63;
            sX[r*68 + c] = X[(size_t)(row0 + r) * Fv + k0 + c];
        }
#pragma unroll
        for (int s = 0; s < 8; s++) {
            int idx4 = tid + 256 * s; int r = idx4 >> 5, c4 = (idx4 & 31) * 4;
            *(float4*)&sK[r*128 + c4] = *(const float4*)&Wk[(size_t)(k0 + r) * Dv + c4];
            *(float4*)&sW[r*128 + c4] = *(const float4*)&Ws[(size_t)(k0 + r) * Dv + c4];
        }
        __syncthreads();
#pragma unroll 8
        for (int kk = 0; kk < 64; kk++) {
            float a[4], b1[8], b2[8];
#pragma unroll
            for (int i = 0; i < 4; i++) a[i] = sX[(ty*4 + i)*68 + kk];
#pragma unroll
            for (int j = 0; j < 8; j++) {
                b1[j] = sK[kk*128 + tx + 16*j];
                b2[j] = sW[kk*128 + tx + 16*j];
            }
#pragma unroll
            for (int i = 0; i < 4; i++)
#pragma unroll
                for (int j = 0; j < 8; j++) {
                    acc1[i][j] += a[i] * b1[j];
                    acc2[i][j] += a[i] * b2[j];
                }
        }
        __syncthreads();
    }
#pragma unroll
    for (int i = 0; i < 4; i++)
#pragma unroll
        for (int j = 0; j < 8; j++) {
            int r = row0 + ty*4 + i, c = tx + 16*j;
            g_Hx0[(size_t)r * Dv + c] = acc1[i][j] + bias[c];
            g_Xs [(size_t)r * Dv + c] = acc2[i][j] + bskip[c];
        }
}

// ---------------------------------------------------------------------------
// K2: Hx = A @ Hx0  (tensor cores, tf32). grid(32, B), 256 thr (8 warps 4x2)
// Block tile: 64 rows x 128 cols, k-loop 2048 in 64-chunks.
// ---------------------------------------------------------------------------
__global__ __launch_bounds__(256, 1) void aggr_mma_kernel(const float* __restrict__ A)
{
    extern __shared__ float sm[];
    float* sBt = sm;            // [64][SB]  Hx0 k-chunk (tf32 bits)
    float* sAt = sBt + 64*SB;   // [64][SA]  A tile (tf32 bits)
    const int tid = threadIdx.x, warp = tid >> 5, lane = tid & 31;
    const int wn = warp >> 1, wd = warp & 1;
    const int lr = lane >> 2, lc = lane & 3;
    const int b = blockIdx.y, n0 = blockIdx.x * 64;
    const float* Ab = A + (size_t)b * Nv * Nv;
    const float* Hb = g_Hx0 + (size_t)b * Nv * Dv;

    float acc[8][4];
#pragma unroll
    for (int j = 0; j < 8; j++)
#pragma unroll
        for (int i = 0; i < 4; i++) acc[j][i] = 0.f;

    for (int kt = 0; kt < Nv/64; kt++) {
        const int k0 = kt * 64;
#pragma unroll
        for (int s = 0; s < 8; s++) {          // Hx0 chunk 64x128
            int idx4 = tid + 256*s; int r = idx4 >> 5, c4 = (idx4 & 31)*4;
            float4 v = *(const float4*)&Hb[(size_t)(k0 + r)*Dv + c4];
            unsigned* d = (unsigned*)&sBt[r*SB + c4];
            d[0]=f2tf(v.x); d[1]=f2tf(v.y); d[2]=f2tf(v.z); d[3]=f2tf(v.w);
        }
#pragma unroll
        for (int s = 0; s < 4; s++) {          // A tile 64x64
            int idx4 = tid + 256*s; int r = idx4 >> 4, c4 = (idx4 & 15)*4;
            float4 v = *(const float4*)&Ab[(size_t)(n0 + r)*Nv + k0 + c4];
            unsigned* d = (unsigned*)&sAt[r*SA + c4];
            d[0]=f2tf(v.x); d[1]=f2tf(v.y); d[2]=f2tf(v.z); d[3]=f2tf(v.w);
        }
        __syncthreads();
#pragma unroll
        for (int ks = 0; ks < 8; ks++) {
            unsigned a[4];
            const float* aw = sAt + (16*wn)*SA;
            a[0] = ldsu(&aw[ lr    *SA + 8*ks + lc    ]);
            a[1] = ldsu(&aw[(lr+8) *SA + 8*ks + lc    ]);
            a[2] = ldsu(&aw[ lr    *SA + 8*ks + lc + 4]);
            a[3] = ldsu(&aw[(lr+8) *SA + 8*ks + lc + 4]);
#pragma unroll
            for (int j = 0; j < 8; j++) {
                unsigned bb[2];
                bb[0] = ldsu(&sBt[(8*ks + lc    )*SB + 64*wd + 8*j + lr]);
                bb[1] = ldsu(&sBt[(8*ks + lc + 4)*SB + 64*wd + 8*j + lr]);
                mma_tf32(acc[j], a, bb);
            }
        }
        __syncthreads();
    }
    float* Ob = g_Hx + ((size_t)b*Nv + n0)*Dv;
#pragma unroll
    for (int j = 0; j < 8; j++) {
        int rr = 16*wn + lr, cc = 64*wd + 8*j + 2*lc;
        *(float2*)&Ob[(size_t)rr    *Dv + cc] = make_float2(acc[j][0], acc[j][1]);
        *(float2*)&Ob[(size_t)(rr+8)*Dv + cc] = make_float2(acc[j][2], acc[j][3]);
    }
}

// ---------------------------------------------------------------------------
// K3: Q[h,b] = Hx[b] @ attn[h]  (tensor cores). grid(32, B, H)
// ---------------------------------------------------------------------------
__global__ __launch_bounds__(256, 1) void q_mma_kernel(const float* __restrict__ attn)
{
    extern __shared__ float sm[];
    float* sBt = sm;            // [64][SB]  attn chunk
    float* sAt = sBt + 64*SB;   // [64][SA]  Hx tile
    const int tid = threadIdx.x, warp = tid >> 5, lane = tid & 31;
    const int wn = warp >> 1, wd = warp & 1;
    const int lr = lane >> 2, lc = lane & 3;
    const int b = blockIdx.y, h = blockIdx.z, n0 = blockIdx.x * 64;
    const float* Hb = g_Hx + (size_t)b * Nv * Dv;
    const float* At = attn + (size_t)h * Dv * Dv;

    float acc[8][4];
#pragma unroll
    for (int j = 0; j < 8; j++)
#pragma unroll
        for (int i = 0; i < 4; i++) acc[j][i] = 0.f;

    for (int kt = 0; kt < Dv/64; kt++) {
        const int k0 = kt * 64;
#pragma unroll
        for (int s = 0; s < 8; s++) {          // attn chunk 64x128
            int idx4 = tid + 256*s; int r = idx4 >> 5, c4 = (idx4 & 31)*4;
            float4 v = *(const float4*)&At[(size_t)(k0 + r)*Dv + c4];
            unsigned* d = (unsigned*)&sBt[r*SB + c4];
            d[0]=f2tf(v.x); d[1]=f2tf(v.y); d[2]=f2tf(v.z); d[3]=f2tf(v.w);
        }
#pragma unroll
        for (int s = 0; s < 4; s++) {          // Hx tile 64x64
            int idx4 = tid + 256*s; int r = idx4 >> 4, c4 = (idx4 & 15)*4;
            float4 v = *(const float4*)&Hb[(size_t)(n0 + r)*Dv + k0 + c4];
            unsigned* d = (unsigned*)&sAt[r*SA + c4];
            d[0]=f2tf(v.x); d[1]=f2tf(v.y); d[2]=f2tf(v.z); d[3]=f2tf(v.w);
        }
        __syncthreads();
#pragma unroll
        for (int ks = 0; ks < 8; ks++) {
            unsigned a[4];
            const float* aw = sAt + (16*wn)*SA;
            a[0] = ldsu(&aw[ lr    *SA + 8*ks + lc    ]);
            a[1] = ldsu(&aw[(lr+8) *SA + 8*ks + lc    ]);
            a[2] = ldsu(&aw[ lr    *SA + 8*ks + lc + 4]);
            a[3] = ldsu(&aw[(lr+8) *SA + 8*ks + lc + 4]);
#pragma unroll
            for (int j = 0; j < 8; j++) {
                unsigned bb[2];
                bb[0] = ldsu(&sBt[(8*ks + lc    )*SB + 64*wd + 8*j + lr]);
                bb[1] = ldsu(&sBt[(8*ks + lc + 4)*SB + 64*wd + 8*j + lr]);
                mma_tf32(acc[j], a, bb);
            }
        }
        __syncthreads();
    }
    float* Ob = g_Q + (((size_t)h*Bv + b)*Nv + n0)*Dv;
#pragma unroll
    for (int j = 0; j < 8; j++) {
        int rr = 16*wn + lr, cc = 64*wd + 8*j + 2*lc;
        *(float2*)&Ob[(size_t)rr    *Dv + cc] = make_float2(acc[j][0], acc[j][1]);
        *(float2*)&Ob[(size_t)(rr+8)*Dv + cc] = make_float2(acc[j][2], acc[j][3]);
    }
}

// ---------------------------------------------------------------------------
// K4: fused attention (tensor cores). grid(32, B), 256 thr.
// acc[n,d] = sum_h sum_m tanh(A[n,m] * (Q_h[n,:]·Hx[m,:])) * Hx[m,d]
// Q for all 4 heads resident in smem; Hx/A tiles loaded once per m-tile.
// ---------------------------------------------------------------------------
__global__ __launch_bounds__(256, 1) void attn_mma_kernel(const float* __restrict__ A)
{
    extern __shared__ float sm[];
    float* sQ  = sm;                 // [4][64][SB]  tf32 Q, all heads
    float* sHx = sQ + 4*64*SB;       // [64][SB]     tf32 Hx m-tile
    float* sAr = sHx + 64*SB;        // [64][SA]     raw A tile (f32)
    float* sAm = sAr + 64*SA;        // [64][SA]     tf32 Am tile
    const int tid = threadIdx.x, warp = tid >> 5, lane = tid & 31;
    const int wn = warp >> 1, wd = warp & 1;
    const int lr = lane >> 2, lc = lane & 3;
    const int b = blockIdx.y, n0 = blockIdx.x * 64;
    const float* Ab = A + (size_t)b * Nv * Nv;
    const float* Hb = g_Hx + (size_t)b * Nv * Dv;

    // Load Q for all heads: 4*64*128 floats = 8192 float4, 32 per thread
#pragma unroll
    for (int s = 0; s < 32; s++) {
        int idx4 = tid + 256*s;
        int h = idx4 >> 11;
        int rem = idx4 & 2047; int r = rem >> 5, c4 = (rem & 31)*4;
        const float* Qb = g_Q + (((size_t)h*Bv + b)*Nv + n0)*Dv;
        float4 v = *(const float4*)&Qb[(size_t)r*Dv + c4];
        unsigned* d = (unsigned*)&sQ[(h*64 + r)*SB + c4];
        d[0]=f2tf(v.x); d[1]=f2tf(v.y); d[2]=f2tf(v.z); d[3]=f2tf(v.w);
    }

    float acc[8][4];
#pragma unroll
    for (int j = 0; j < 8; j++)
#pragma unroll
        for (int i = 0; i < 4; i++) acc[j][i] = 0.f;

    for (int mt = 0; mt < Nv/64; mt++) {
        const int m0 = mt * 64;
        // Hx m-tile 64x128 (tf32)
#pragma unroll
        for (int s = 0; s < 8; s++) {
            int idx4 = tid + 256*s; int r = idx4 >> 5, c4 = (idx4 & 31)*4;
            float4 v = *(const float4*)&Hb[(size_t)(m0 + r)*Dv + c4];
            unsigned* d = (unsigned*)&sHx[r*SB + c4];
            d[0]=f2tf(v.x); d[1]=f2tf(v.y); d[2]=f2tf(v.z); d[3]=f2tf(v.w);
        }
        // A tile 64x64 (raw f32)
#pragma unroll
        for (int s = 0; s < 4; s++) {
            int idx4 = tid + 256*s; int r = idx4 >> 4, c4 = (idx4 & 15)*4;
            *(float4*)&sAr[r*SA + c4] =
                *(const float4*)&Ab[(size_t)(n0 + r)*Nv + m0 + c4];
        }
        __syncthreads();

        for (int h = 0; h < Hv; h++) {
            // GEMM1: S(16 rows x 32 m-cols per warp) = Q_h · Hx^T
            float s4[4][4];
#pragma unroll
            for (int j = 0; j < 4; j++)
#pragma unroll
                for (int i = 0; i < 4; i++) s4[j][i] = 0.f;
            const float* sQh = sQ + (h*64 + 16*wn)*SB;
#pragma unroll
            for (int ks = 0; ks < 16; ks++) {
                unsigned a[4];
                a[0] = ldsu(&sQh[ lr    *SB + 8*ks + lc    ]);
                a[1] = ldsu(&sQh[(lr+8) *SB + 8*ks + lc    ]);
                a[2] = ldsu(&sQh[ lr    *SB + 8*ks + lc + 4]);
                a[3] = ldsu(&sQh[(lr+8) *SB + 8*ks + lc + 4]);
#pragma unroll
                for (int j = 0; j < 4; j++) {
                    unsigned bb[2];
                    int m = 32*wd + 8*j + lr;
                    bb[0] = ldsu(&sHx[m*SB + 8*ks + lc    ]);
                    bb[1] = ldsu(&sHx[m*SB + 8*ks + lc + 4]);
                    mma_tf32(s4[j], a, bb);
                }
            }
            // Am = tf32(tanh(A * S)) — each thread owns its S elements
#pragma unroll
            for (int j = 0; j < 4; j++) {
                int rr = 16*wn + lr;
                int cc = 32*wd + 8*j + 2*lc;
                float2 a01 = *(const float2*)&sAr[ rr   *SA + cc];
                float2 a23 = *(const float2*)&sAr[(rr+8)*SA + cc];
                unsigned m0v = f2tf(tanh_fast(a01.x * s4[j][0]));
                unsigned m1v = f2tf(tanh_fast(a01.y * s4[j][1]));
                unsigned m2v = f2tf(tanh_fast(a23.x * s4[j][2]));
                unsigned m3v = f2tf(tanh_fast(a23.y * s4[j][3]));
                *(uint2*)&sAm[ rr   *SA + cc] = make_uint2(m0v, m1v);
                *(uint2*)&sAm[(rr+8)*SA + cc] = make_uint2(m2v, m3v);
            }
            __syncthreads();
            // GEMM2: acc(16 rows x 64 d-cols per warp) += Am · Hx
#pragma unroll
            for (int ks = 0; ks < 8; ks++) {
                unsigned a[4];
                const float* aw = sAm + (16*wn)*SA;
                a[0] = ldsu(&aw[ lr    *SA + 8*ks + lc    ]);
                a[1] = ldsu(&aw[(lr+8) *SA + 8*ks + lc    ]);
                a[2] = ldsu(&aw[ lr    *SA + 8*ks + lc + 4]);
                a[3] = ldsu(&aw[(lr+8) *SA + 8*ks + lc + 4]);
#pragma unroll
                for (int j = 0; j < 8; j++) {
                    unsigned bb[2];
                    bb[0] = ldsu(&sHx[(8*ks + lc    )*SB + 64*wd + 8*j + lr]);
                    bb[1] = ldsu(&sHx[(8*ks + lc + 4)*SB + 64*wd + 8*j + lr]);
                    mma_tf32(acc[j], a, bb);
                }
            }
            __syncthreads();   // protects sAm (next h) and sHx/sAr (next mt)
        }
    }
    // Hout = relu(acc / H)
    float* Ho = g_Hout + ((size_t)b*Nv + n0)*Dv;
#pragma unroll
    for (int j = 0; j < 8; j++) {
        int rr = 16*wn + lr, cc = 64*wd + 8*j + 2*lc;
        float v0 = fmaxf(acc[j][0] * 0.25f, 0.f);
        float v1 = fmaxf(acc[j][1] * 0.25f, 0.f);
        float v2 = fmaxf(acc[j][2] * 0.25f, 0.f);
        float v3 = fmaxf(acc[j][3] * 0.25f, 0.f);
        *(float2*)&Ho[(size_t)rr    *Dv + cc] = make_float2(v0, v1);
        *(float2*)&Ho[(size_t)(rr+8)*Dv + cc] = make_float2(v2, v3);
    }
}

// ---------------------------------------------------------------------------
// K5: z = sigmoid(Hout@W_u + Xs@W_x + biases); out = Hout*z + Xs*(1-z)  (SIMT)
// ---------------------------------------------------------------------------
__global__ __launch_bounds__(256) void gate_kernel(
    const float* __restrict__ Wu, const float* __restrict__ bu,
    const float* __restrict__ Wx, const float* __restrict__ bx,
    const float* __restrict__ ub, float* __restrict__ out)
{
    extern __shared__ float sm[];
    float* sHo = sm;              // [64][132]
    float* sXs = sHo + 64*132;    // [64][132]
    float* sWu = sXs + 64*132;    // [64][128]
    float* sWx = sWu + 64*128;    // [64][128]
    const int tid = threadIdx.x, ty = tid >> 4, tx = tid & 15;
    const int row0 = blockIdx.x * 64;

#pragma unroll
    for (int s = 0; s < 8; s++) {
        int idx4 = tid + 256 * s; int r = idx4 >> 5, c4 = (idx4 & 31) * 4;
        *(float4*)&sHo[r*132 + c4] = *(const float4*)&g_Hout[(size_t)(row0 + r) * Dv + c4];
        *(float4*)&sXs[r*132 + c4] = *(const float4*)&g_Xs  [(size_t)(row0 + r) * Dv + c4];
    }

    float acc[4][8];
#pragma unroll
    for (int i = 0; i < 4; i++)
#pragma unroll
        for (int j = 0; j < 8; j++) acc[i][j] = 0.f;

    for (int k0 = 0; k0 < Dv; k0 += 64) {
#pragma unroll
        for (int s = 0; s < 8; s++) {
            int idx4 = tid + 256 * s; int r = idx4 >> 5, c4 = (idx4 & 31) * 4;
            *(float4*)&sWu[r*128 + c4] = *(const float4*)&Wu[(size_t)(k0 + r) * Dv + c4];
            *(float4*)&sWx[r*128 + c4] = *(const float4*)&Wx[(size_t)(k0 + r) * Dv + c4];
        }
        __syncthreads();
#pragma unroll 8
        for (int kk = 0; kk < 64; kk++) {
            float a1[4], a2[4], b1[8], b2[8];
#pragma unroll
            for (int i = 0; i < 4; i++) {
                a1[i] = sHo[(ty*4 + i)*132 + k0 + kk];
                a2[i] = sXs[(ty*4 + i)*132 + k0 + kk];
            }
#pragma unroll
            for (int j = 0; j < 8; j++) {
                b1[j] = sWu[kk*128 + tx + 16*j];
                b2[j] = sWx[kk*128 + tx + 16*j];
            }
#pragma unroll
            for (int i = 0; i < 4; i++)
#pragma unroll
                for (int j = 0; j < 8; j++)
                    acc[i][j] += a1[i] * b1[j] + a2[i] * b2[j];
        }
        __syncthreads();
    }
#pragma unroll
    for (int i = 0; i < 4; i++)
#pragma unroll
        for (int j = 0; j < 8; j++) {
            int r = ty*4 + i, c = tx + 16*j;
            float ho = sHo[r*132 + c];
            float xs = sXs[r*132 + c];
            float zl = acc[i][j] + bu[c] + bx[c] + ub[c];
            float z = 1.f / (1.f + expf(-zl));
            out[(size_t)(row0 + r) * Dv + c] = ho * z + xs * (1.f - z);
        }
}

// ---------------------------------------------------------------------------
extern "C" void kernel_launch(void* const* d_in, const int* in_sizes, int n_in,
                              void* d_out, int out_size)
{
    const float* X      = (const float*)d_in[0];
    const float* A      = (const float*)d_in[1];
    const float* Wk     = (const float*)d_in[2];
    const float* bias   = (const float*)d_in[3];
    const float* ub     = (const float*)d_in[4];
    const float* attn   = (const float*)d_in[5];
    const float* Wskip  = (const float*)d_in[6];
    const float* bskip  = (const float*)d_in[7];
    const float* Wu     = (const float*)d_in[8];
    const float* bu     = (const float*)d_in[9];
    const float* Wx     = (const float*)d_in[10];
    const float* bx     = (const float*)d_in[11];
    float* out = (float*)d_out;

    const int SM1 = (64*68 + 2*64*128) * 4;
    const int SM2 = (64*SB + 64*SA) * 4;
    const int SM3 = (64*SB + 64*SA) * 4;
    const int SM4 = (4*64*SB + 64*SB + 2*64*SA) * 4;
    const int SM5 = (2*64*132 + 2*64*128) * 4;
    cudaFuncSetAttribute(proj_kernel,     cudaFuncAttributeMaxDynamicSharedMemorySize, SM1);
    cudaFuncSetAttribute(aggr_mma_kernel, cudaFuncAttributeMaxDynamicSharedMemorySize, SM2);
    cudaFuncSetAttribute(q_mma_kernel,    cudaFuncAttributeMaxDynamicSharedMemorySize, SM3);
    cudaFuncSetAttribute(attn_mma_kernel, cudaFuncAttributeMaxDynamicSharedMemorySize, SM4);
    cudaFuncSetAttribute(gate_kernel,     cudaFuncAttributeMaxDynamicSharedMemorySize, SM5);

    proj_kernel    <<<(Bv*Nv)/64, 256, SM1>>>(X, Wk, bias, Wskip, bskip);
    aggr_mma_kernel<<<dim3(Nv/64, Bv),     256, SM2>>>(A);
    q_mma_kernel   <<<dim3(Nv/64, Bv, Hv), 256, SM3>>>(attn);
    attn_mma_kernel<<<dim3(Nv/64, Bv),     256, SM4>>>(A);
    gate_kernel    <<<(Bv*Nv)/64, 256, SM5>>>(Wu, bu, Wx, bx, ub, out);

    // Second tuple element: copy A into the tail of the output buffer.
    cudaMemcpyAsync(out + (size_t)Bv*Nv*Dv, A,
                    (size_t)Bv*Nv*Nv * sizeof(float),
                    cudaMemcpyDeviceToDevice);
}

// round 4
// speedup vs baseline: 4.2054x; 1.4903x over previous
#include <cuda_runtime.h>
#include <cuda_bf16.h>
#include <math.h>
#include <stdint.h>

#define Bv 4
#define Nv 2048
#define Fv 256
#define Dv 128
#define Hv 4

// Scratch (device globals per harness rules)
__device__ float g_Hx0 [Bv*Nv*Dv];             // X@kernel + bias
__device__ float g_Hx  [Bv*Nv*Dv];             // A @ Hx0 (f32, for q_kernel)
__device__ float g_Xs  [Bv*Nv*Dv];             // X@W_skip + b_skip
__device__ float g_Hout[Bv*Nv*Dv];             // relu(mean_h heads)
__device__ __nv_bfloat16 g_Hxb[Bv*Nv*Dv];      // Hx bf16 [b][n][d]  (d-pairs)
__device__ __nv_bfloat16 g_HxT[Bv*Dv*Nv];      // Hx bf16 [b][d][n]  (n-pairs)
__device__ __nv_bfloat16 g_Qb [Hv*Bv*Nv*Dv];   // Q  bf16 [h][b][n][d]

// ---------------------------------------------------------------------------
// helpers
// ---------------------------------------------------------------------------
__device__ __forceinline__ unsigned f2tf(float f) {
    unsigned u; asm("cvt.rna.tf32.f32 %0, %1;" : "=r"(u) : "f"(f)); return u;
}
__device__ __forceinline__ float tanh_fast(float x) {
    float y; asm("tanh.approx.f32 %0, %1;" : "=f"(y) : "f"(x)); return y;
}
__device__ __forceinline__ unsigned pack_bf16(float lo, float hi) {
    unsigned d; asm("cvt.rn.bf16x2.f32 %0, %1, %2;" : "=r"(d) : "f"(hi), "f"(lo)); return d;
}
__device__ __forceinline__ void mma_tf32(float c[4], const unsigned a[4], const unsigned b[2]) {
    asm volatile(
        "mma.sync.aligned.m16n8k8.row.col.f32.tf32.tf32.f32 "
        "{%0,%1,%2,%3}, {%4,%5,%6,%7}, {%8,%9}, {%0,%1,%2,%3};"
        : "+f"(c[0]), "+f"(c[1]), "+f"(c[2]), "+f"(c[3])
        : "r"(a[0]), "r"(a[1]), "r"(a[2]), "r"(a[3]), "r"(b[0]), "r"(b[1]));
}
__device__ __forceinline__ void mma_bf16(float c[4], const unsigned a[4], const unsigned b[2]) {
    asm volatile(
        "mma.sync.aligned.m16n8k16.row.col.f32.bf16.bf16.f32 "
        "{%0,%1,%2,%3}, {%4,%5,%6,%7}, {%8,%9}, {%0,%1,%2,%3};"
        : "+f"(c[0]), "+f"(c[1]), "+f"(c[2]), "+f"(c[3])
        : "r"(a[0]), "r"(a[1]), "r"(a[2]), "r"(a[3]), "r"(b[0]), "r"(b[1]));
}
__device__ __forceinline__ unsigned ldsu(const float* p) { return __float_as_uint(*p); }

// tf32 kernels (aggr/q): SB=140, SA=68 (conflict-free, see R3)
#define SB 140
#define SA 68
// bf16 attn kernel strides in 32-bit WORDS (4*lr+lc mod 32 -> conflict-free)
#define WQ 68   // k-words per row for sQ/sHx (64 + 4 pad)
#define WT 36   // m-words per row for sHxT/sAm (32 + 4 pad)

// ---------------------------------------------------------------------------
// K1: Hx0 = X@kernel + bias   and   Xs = X@W_skip + b_skip   (SIMT, small)
// ---------------------------------------------------------------------------
__global__ __launch_bounds__(256) void proj_kernel(
    const float* __restrict__ X, const float* __restrict__ Wk,
    const float* __restrict__ bias, const float* __restrict__ Ws,
    const float* __restrict__ bskip)
{
    extern __shared__ float sm[];
    float* sX = sm;             // [64][68]
    float* sK = sX + 64*68;     // [64][128]
    float* sW = sK + 64*128;    // [64][128]
    const int tid = threadIdx.x, ty = tid >> 4, tx = tid & 15;
    const int row0 = blockIdx.x * 64;

    float acc1[4][8], acc2[4][8];
#pragma unroll
    for (int i = 0; i < 4; i++)
#pragma unroll
        for (int j = 0; j < 8; j++) { acc1[i][j] = 0.f; acc2[i][j] = 0.f; }

    for (int k0 = 0; k0 < Fv; k0 += 64) {
#pragma unroll
        for (int s = 0; s < 16; s++) {
            int idx = tid + 256 * s; int r = idx >> 6, c = idx & 63;
            sX[r*68 + c] = X[(size_t)(row0 + r) * Fv + k0 + c];
        }
#pragma unroll
        for (int s = 0; s < 8; s++) {
            int idx4 = tid + 256 * s; int r = idx4 >> 5, c4 = (idx4 & 31) * 4;
            *(float4*)&sK[r*128 + c4] = *(const float4*)&Wk[(size_t)(k0 + r) * Dv + c4];
            *(float4*)&sW[r*128 + c4] = *(const float4*)&Ws[(size_t)(k0 + r) * Dv + c4];
        }
        __syncthreads();
#pragma unroll 8
        for (int kk = 0; kk < 64; kk++) {
            float a[4], b1[8], b2[8];
#pragma unroll
            for (int i = 0; i < 4; i++) a[i] = sX[(ty*4 + i)*68 + kk];
#pragma unroll
            for (int j = 0; j < 8; j++) {
                b1[j] = sK[kk*128 + tx + 16*j];
                b2[j] = sW[kk*128 + tx + 16*j];
            }
#pragma unroll
            for (int i = 0; i < 4; i++)
#pragma unroll
                for (int j = 0; j < 8; j++) {
                    acc1[i][j] += a[i] * b1[j];
                    acc2[i][j] += a[i] * b2[j];
                }
        }
        __syncthreads();
    }
#pragma unroll
    for (int i = 0; i < 4; i++)
#pragma unroll
        for (int j = 0; j < 8; j++) {
            int r = row0 + ty*4 + i, c = tx + 16*j;
            g_Hx0[(size_t)r * Dv + c] = acc1[i][j] + bias[c];
            g_Xs [(size_t)r * Dv + c] = acc2[i][j] + bskip[c];
        }
}

// ---------------------------------------------------------------------------
// K2: Hx = A @ Hx0  (tf32 mma). Epilogue writes f32 + bf16 + bf16-transposed.
// ---------------------------------------------------------------------------
__global__ __launch_bounds__(256, 1) void aggr_mma_kernel(const float* __restrict__ A)
{
    extern __shared__ float sm[];
    float* sBt = sm;            // [64][SB]  Hx0 k-chunk (tf32 bits)
    float* sAt = sBt + 64*SB;   // [64][SA]  A tile (tf32 bits)
    const int tid = threadIdx.x, warp = tid >> 5, lane = tid & 31;
    const int wn = warp >> 1, wd = warp & 1;
    const int lr = lane >> 2, lc = lane & 3;
    const int b = blockIdx.y, n0 = blockIdx.x * 64;
    const float* Ab = A + (size_t)b * Nv * Nv;
    const float* Hb = g_Hx0 + (size_t)b * Nv * Dv;

    float acc[8][4];
#pragma unroll
    for (int j = 0; j < 8; j++)
#pragma unroll
        for (int i = 0; i < 4; i++) acc[j][i] = 0.f;

    for (int kt = 0; kt < Nv/64; kt++) {
        const int k0 = kt * 64;
#pragma unroll
        for (int s = 0; s < 8; s++) {          // Hx0 chunk 64x128
            int idx4 = tid + 256*s; int r = idx4 >> 5, c4 = (idx4 & 31)*4;
            float4 v = *(const float4*)&Hb[(size_t)(k0 + r)*Dv + c4];
            unsigned* d = (unsigned*)&sBt[r*SB + c4];
            d[0]=f2tf(v.x); d[1]=f2tf(v.y); d[2]=f2tf(v.z); d[3]=f2tf(v.w);
        }
#pragma unroll
        for (int s = 0; s < 4; s++) {          // A tile 64x64
            int idx4 = tid + 256*s; int r = idx4 >> 4, c4 = (idx4 & 15)*4;
            float4 v = *(const float4*)&Ab[(size_t)(n0 + r)*Nv + k0 + c4];
            unsigned* d = (unsigned*)&sAt[r*SA + c4];
            d[0]=f2tf(v.x); d[1]=f2tf(v.y); d[2]=f2tf(v.z); d[3]=f2tf(v.w);
        }
        __syncthreads();
#pragma unroll
        for (int ks = 0; ks < 8; ks++) {
            unsigned a[4];
            const float* aw = sAt + (16*wn)*SA;
            a[0] = ldsu(&aw[ lr    *SA + 8*ks + lc    ]);
            a[1] = ldsu(&aw[(lr+8) *SA + 8*ks + lc    ]);
            a[2] = ldsu(&aw[ lr    *SA + 8*ks + lc + 4]);
            a[3] = ldsu(&aw[(lr+8) *SA + 8*ks + lc + 4]);
#pragma unroll
            for (int j = 0; j < 8; j++) {
                unsigned bb[2];
                bb[0] = ldsu(&sBt[(8*ks + lc    )*SB + 64*wd + 8*j + lr]);
                bb[1] = ldsu(&sBt[(8*ks + lc + 4)*SB + 64*wd + 8*j + lr]);
                mma_tf32(acc[j], a, bb);
            }
        }
        __syncthreads();
    }
    float* Ob = g_Hx + ((size_t)b*Nv + n0)*Dv;
    unsigned* Pb = (unsigned*)g_Hxb;   // word-packed [b][n][d/2]
    __nv_bfloat16* Tb = g_HxT + (size_t)b * Dv * Nv;
#pragma unroll
    for (int j = 0; j < 8; j++) {
        int rr = 16*wn + lr, cc = 64*wd + 8*j + 2*lc;
        *(float2*)&Ob[(size_t)rr    *Dv + cc] = make_float2(acc[j][0], acc[j][1]);
        *(float2*)&Ob[(size_t)(rr+8)*Dv + cc] = make_float2(acc[j][2], acc[j][3]);
        // packed bf16 [n][d]
        Pb[(((size_t)b*Nv + n0+rr  )*Dv + cc) >> 1] = pack_bf16(acc[j][0], acc[j][1]);
        Pb[(((size_t)b*Nv + n0+rr+8)*Dv + cc) >> 1] = pack_bf16(acc[j][2], acc[j][3]);
        // transposed bf16 [d][n]
        Tb[(size_t)(cc  )*Nv + n0+rr  ] = __float2bfloat16(acc[j][0]);
        Tb[(size_t)(cc+1)*Nv + n0+rr  ] = __float2bfloat16(acc[j][1]);
        Tb[(size_t)(cc  )*Nv + n0+rr+8] = __float2bfloat16(acc[j][2]);
        Tb[(size_t)(cc+1)*Nv + n0+rr+8] = __float2bfloat16(acc[j][3]);
    }
}

// ---------------------------------------------------------------------------
// K3: Q[h,b] = Hx[b] @ attn[h]  (tf32 mma) -> bf16 packed output
// ---------------------------------------------------------------------------
__global__ __launch_bounds__(256, 1) void q_mma_kernel(const float* __restrict__ attn)
{
    extern __shared__ float sm[];
    float* sBt = sm;            // [64][SB]  attn chunk
    float* sAt = sBt + 64*SB;   // [64][SA]  Hx tile
    const int tid = threadIdx.x, warp = tid >> 5, lane = tid & 31;
    const int wn = warp >> 1, wd = warp & 1;
    const int lr = lane >> 2, lc = lane & 3;
    const int b = blockIdx.y, h = blockIdx.z, n0 = blockIdx.x * 64;
    const float* Hb = g_Hx + (size_t)b * Nv * Dv;
    const float* At = attn + (size_t)h * Dv * Dv;

    float acc[8][4];
#pragma unroll
    for (int j = 0; j < 8; j++)
#pragma unroll
        for (int i = 0; i < 4; i++) acc[j][i] = 0.f;

    for (int kt = 0; kt < Dv/64; kt++) {
        const int k0 = kt * 64;
#pragma unroll
        for (int s = 0; s < 8; s++) {          // attn chunk 64x128
            int idx4 = tid + 256*s; int r = idx4 >> 5, c4 = (idx4 & 31)*4;
            float4 v = *(const float4*)&At[(size_t)(k0 + r)*Dv + c4];
            unsigned* d = (unsigned*)&sBt[r*SB + c4];
            d[0]=f2tf(v.x); d[1]=f2tf(v.y); d[2]=f2tf(v.z); d[3]=f2tf(v.w);
        }
#pragma unroll
        for (int s = 0; s < 4; s++) {          // Hx tile 64x64
            int idx4 = tid + 256*s; int r = idx4 >> 4, c4 = (idx4 & 15)*4;
            float4 v = *(const float4*)&Hb[(size_t)(n0 + r)*Dv + k0 + c4];
            unsigned* d = (unsigned*)&sAt[r*SA + c4];
            d[0]=f2tf(v.x); d[1]=f2tf(v.y); d[2]=f2tf(v.z); d[3]=f2tf(v.w);
        }
        __syncthreads();
#pragma unroll
        for (int ks = 0; ks < 8; ks++) {
            unsigned a[4];
            const float* aw = sAt + (16*wn)*SA;
            a[0] = ldsu(&aw[ lr    *SA + 8*ks + lc    ]);
            a[1] = ldsu(&aw[(lr+8) *SA + 8*ks + lc    ]);
            a[2] = ldsu(&aw[ lr    *SA + 8*ks + lc + 4]);
            a[3] = ldsu(&aw[(lr+8) *SA + 8*ks + lc + 4]);
#pragma unroll
            for (int j = 0; j < 8; j++) {
                unsigned bb[2];
                bb[0] = ldsu(&sBt[(8*ks + lc    )*SB + 64*wd + 8*j + lr]);
                bb[1] = ldsu(&sBt[(8*ks + lc + 4)*SB + 64*wd + 8*j + lr]);
                mma_tf32(acc[j], a, bb);
            }
        }
        __syncthreads();
    }
    unsigned* Ob = (unsigned*)g_Qb;
#pragma unroll
    for (int j = 0; j < 8; j++) {
        int rr = 16*wn + lr, cc = 64*wd + 8*j + 2*lc;
        Ob[((((size_t)h*Bv + b)*Nv + n0+rr  )*Dv + cc) >> 1] = pack_bf16(acc[j][0], acc[j][1]);
        Ob[((((size_t)h*Bv + b)*Nv + n0+rr+8)*Dv + cc) >> 1] = pack_bf16(acc[j][2], acc[j][3]);
    }
}

// ---------------------------------------------------------------------------
// K4: fused attention, bf16 m16n8k16 tensor cores. grid(32, B), 256 thr.
// acc[n,d] = sum_h sum_m tanh(A[n,m] * (Q_h[n,:].Hx[m,:])) * Hx[m,d]
// GEMM1 warps: (2 wn x 4 wm), warp tile 32n x 16m, full K=128.
// GEMM2 warps: (2 wn x 2 wd x 2 wk), warp tile 32n x 64d, k-half 32m.
// ---------------------------------------------------------------------------
__global__ __launch_bounds__(256, 1) void attn_bf16_kernel(const float* __restrict__ A)
{
    extern __shared__ unsigned smw[];
    unsigned* sQ   = smw;                 // [4][64][WQ] words (bf16 pairs, k-paired)
    unsigned* sHx  = sQ  + 4*64*WQ;       // [64][WQ]   Hx m-tile [m][k-words]
    unsigned* sHxT = sHx + 64*WQ;         // [128][WT]  Hx^T [d][m-words]
    unsigned* sAm  = sHxT + 128*WT;       // [64][WT]   Am  [n][m-words]
    float*    sAr  = (float*)(sAm + 64*WT); // [64][68] raw A tile f32

    const int tid = threadIdx.x, warp = tid >> 5, lane = tid & 31;
    const int lr = lane >> 2, lc = lane & 3;
    // GEMM1 roles
    const int g1n = warp & 1, g1m = (warp >> 1) & 3;
    // GEMM2 roles
    const int g2n = warp & 1, g2d = (warp >> 1) & 1, g2k = warp >> 2;
    const int b = blockIdx.y, n0 = blockIdx.x * 64;
    const float* Ab = A + (size_t)b * Nv * Nv;
    const unsigned* HbW = (const unsigned*)g_Hxb + (size_t)b * Nv * (Dv/2);
    const unsigned* HtW = (const unsigned*)g_HxT + (size_t)b * Dv * (Nv/2);

    // ---- load Q (all 4 heads) : 4*64*64 words = 4096 uint4
#pragma unroll
    for (int s = 0; s < 16; s++) {
        int i4 = tid + 256*s;
        int h = i4 >> 10, r = (i4 >> 4) & 63, c4 = (i4 & 15) * 4;
        const uint4* src = (const uint4*)((const unsigned*)g_Qb +
            (((size_t)h*Bv + b)*Nv + n0 + r) * (Dv/2));
        uint4 v = src[c4 >> 2];
        *(uint4*)&sQ[(h*64 + r)*WQ + c4] = v;
    }

    float acc[2][8][4];
#pragma unroll
    for (int f = 0; f < 2; f++)
#pragma unroll
        for (int j = 0; j < 8; j++)
#pragma unroll
            for (int i = 0; i < 4; i++) acc[f][j][i] = 0.f;

    for (int mt = 0; mt < Nv/64; mt++) {
        const int m0 = mt * 64;
        // sHx: 64 rows x 64 words  (16 uint4 per row)
#pragma unroll
        for (int s = 0; s < 4; s++) {
            int i4 = tid + 256*s;
            int r = i4 >> 4, c4 = (i4 & 15) * 4;
            uint4 v = *(const uint4*)&HbW[(size_t)(m0 + r)*(Dv/2) + c4];
            *(uint4*)&sHx[r*WQ + c4] = v;
        }
        // sHxT: 128 rows x 32 words (8 uint4 per row)
#pragma unroll
        for (int s = 0; s < 4; s++) {
            int i4 = tid + 256*s;
            int d = i4 >> 3, c4 = (i4 & 7) * 4;
            uint4 v = *(const uint4*)&HtW[(size_t)d*(Nv/2) + (m0 >> 1) + c4];
            *(uint4*)&sHxT[d*WT + c4] = v;
        }
        // sAr: raw A tile 64x64 f32
#pragma unroll
        for (int s = 0; s < 4; s++) {
            int i4 = tid + 256*s; int r = i4 >> 4, c4 = (i4 & 15)*4;
            *(float4*)&sAr[r*68 + c4] =
                *(const float4*)&Ab[(size_t)(n0 + r)*Nv + m0 + c4];
        }
        __syncthreads();

        for (int h = 0; h < Hv; h++) {
            // ---- GEMM1: S(32n x 16m per warp) = Q_h . Hx^T, bf16 k16
            float s4[2][2][4];
#pragma unroll
            for (int f = 0; f < 2; f++)
#pragma unroll
                for (int jm = 0; jm < 2; jm++)
#pragma unroll
                    for (int i = 0; i < 4; i++) s4[f][jm][i] = 0.f;
            const unsigned* q = sQ + (h*64 + g1n*32)*WQ;
#pragma unroll
            for (int ks = 0; ks < 8; ks++) {
                unsigned a0[4], a1[4];
                a0[0] = q[( lr    )*WQ + 8*ks + lc    ];
                a0[1] = q[( lr+8  )*WQ + 8*ks + lc    ];
                a0[2] = q[( lr    )*WQ + 8*ks + lc + 4];
                a0[3] = q[( lr+8  )*WQ + 8*ks + lc + 4];
                a1[0] = q[(16+lr  )*WQ + 8*ks + lc    ];
                a1[1] = q[(16+lr+8)*WQ + 8*ks + lc    ];
                a1[2] = q[(16+lr  )*WQ + 8*ks + lc + 4];
                a1[3] = q[(16+lr+8)*WQ + 8*ks + lc + 4];
#pragma unroll
                for (int jm = 0; jm < 2; jm++) {
                    unsigned bb[2];
                    int m = g1m*16 + jm*8 + lr;
                    bb[0] = sHx[m*WQ + 8*ks + lc    ];
                    bb[1] = sHx[m*WQ + 8*ks + lc + 4];
                    mma_bf16(s4[0][jm], a0, bb);
                    mma_bf16(s4[1][jm], a1, bb);
                }
            }
            // ---- Am = bf16(tanh(A * S)) -> sAm [n][m-words]
#pragma unroll
            for (int f = 0; f < 2; f++)
#pragma unroll
                for (int jm = 0; jm < 2; jm++) {
                    int n  = g1n*32 + f*16 + lr;
                    int mm = g1m*16 + jm*8 + 2*lc;
                    float2 a01 = *(const float2*)&sAr[ n    *68 + mm];
                    float2 a23 = *(const float2*)&sAr[(n+8) *68 + mm];
                    sAm[ n    *WT + (mm >> 1)] =
                        pack_bf16(tanh_fast(a01.x * s4[f][jm][0]),
                                  tanh_fast(a01.y * s4[f][jm][1]));
                    sAm[(n+8) *WT + (mm >> 1)] =
                        pack_bf16(tanh_fast(a23.x * s4[f][jm][2]),
                                  tanh_fast(a23.y * s4[f][jm][3]));
                }
            __syncthreads();
            // ---- GEMM2: acc(32n x 64d per warp, k-half) += Am . Hx, bf16 k16
#pragma unroll
            for (int ks = 0; ks < 2; ks++) {
                int kw = g2k*16 + ks*8;
                unsigned a0[4], a1[4];
                const unsigned* am = sAm + (g2n*32)*WT;
                a0[0] = am[( lr    )*WT + kw + lc    ];
                a0[1] = am[( lr+8  )*WT + kw + lc    ];
                a0[2] = am[( lr    )*WT + kw + lc + 4];
                a0[3] = am[( lr+8  )*WT + kw + lc + 4];
                a1[0] = am[(16+lr  )*WT + kw + lc    ];
                a1[1] = am[(16+lr+8)*WT + kw + lc    ];
                a1[2] = am[(16+lr  )*WT + kw + lc + 4];
                a1[3] = am[(16+lr+8)*WT + kw + lc + 4];
#pragma unroll
                for (int j = 0; j < 8; j++) {
                    unsigned bb[2];
                    int d = g2d*64 + j*8 + lr;
                    bb[0] = sHxT[d*WT + kw + lc    ];
                    bb[1] = sHxT[d*WT + kw + lc + 4];
                    mma_bf16(acc[0][j], a0, bb);
                    mma_bf16(acc[1][j], a1, bb);
                }
            }
            __syncthreads();   // protect sAm (next h) / tiles (next mt)
        }
    }

    // ---- reduce wk partial sums (warp w pairs with w+4), then Hout
    float* red = (float*)sQ;   // reuse: 4 pairs * 32 lanes * 64 floats = 32KB
    if (g2k == 1) {
        int base = (((warp - 4) * 32) + lane) * 64;
#pragma unroll
        for (int f = 0; f < 2; f++)
#pragma unroll
            for (int j = 0; j < 8; j++)
#pragma unroll
                for (int i = 0; i < 4; i++)
                    red[base + f*32 + j*4 + i] = acc[f][j][i];
    }
    __syncthreads();
    if (g2k == 0) {
        int base = ((warp * 32) + lane) * 64;
        float* Ho = g_Hout + ((size_t)b*Nv + n0)*Dv;
#pragma unroll
        for (int f = 0; f < 2; f++)
#pragma unroll
            for (int j = 0; j < 8; j++) {
                float v0 = (acc[f][j][0] + red[base + f*32 + j*4 + 0]) * 0.25f;
                float v1 = (acc[f][j][1] + red[base + f*32 + j*4 + 1]) * 0.25f;
                float v2 = (acc[f][j][2] + red[base + f*32 + j*4 + 2]) * 0.25f;
                float v3 = (acc[f][j][3] + red[base + f*32 + j*4 + 3]) * 0.25f;
                int n  = g2n*32 + f*16 + lr;
                int cc = g2d*64 + j*8 + 2*lc;
                *(float2*)&Ho[(size_t)n    *Dv + cc] =
                    make_float2(fmaxf(v0, 0.f), fmaxf(v1, 0.f));
                *(float2*)&Ho[(size_t)(n+8)*Dv + cc] =
                    make_float2(fmaxf(v2, 0.f), fmaxf(v3, 0.f));
            }
    }
}

// ---------------------------------------------------------------------------
// K5: z = sigmoid(Hout@W_u + Xs@W_x + biases); out = Hout*z + Xs*(1-z)  (SIMT)
// ---------------------------------------------------------------------------
__global__ __launch_bounds__(256) void gate_kernel(
    const float* __restrict__ Wu, const float* __restrict__ bu,
    const float* __restrict__ Wx, const float* __restrict__ bx,
    const float* __restrict__ ub, float* __restrict__ out)
{
    extern __shared__ float sm[];
    float* sHo = sm;              // [64][132]
    float* sXs = sHo + 64*132;    // [64][132]
    float* sWu = sXs + 64*132;    // [64][128]
    float* sWx = sWu + 64*128;    // [64][128]
    const int tid = threadIdx.x, ty = tid >> 4, tx = tid & 15;
    const int row0 = blockIdx.x * 64;

#pragma unroll
    for (int s = 0; s < 8; s++) {
        int idx4 = tid + 256 * s; int r = idx4 >> 5, c4 = (idx4 & 31) * 4;
        *(float4*)&sHo[r*132 + c4] = *(const float4*)&g_Hout[(size_t)(row0 + r) * Dv + c4];
        *(float4*)&sXs[r*132 + c4] = *(const float4*)&g_Xs  [(size_t)(row0 + r) * Dv + c4];
    }

    float acc[4][8];
#pragma unroll
    for (int i = 0; i < 4; i++)
#pragma unroll
        for (int j = 0; j < 8; j++) acc[i][j] = 0.f;

    for (int k0 = 0; k0 < Dv; k0 += 64) {
#pragma unroll
        for (int s = 0; s < 8; s++) {
            int idx4 = tid + 256 * s; int r = idx4 >> 5, c4 = (idx4 & 31) * 4;
            *(float4*)&sWu[r*128 + c4] = *(const float4*)&Wu[(size_t)(k0 + r) * Dv + c4];
            *(float4*)&sWx[r*128 + c4] = *(const float4*)&Wx[(size_t)(k0 + r) * Dv + c4];
        }
        __syncthreads();
#pragma unroll 8
        for (int kk = 0; kk < 64; kk++) {
            float a1[4], a2[4], b1[8], b2[8];
#pragma unroll
            for (int i = 0; i < 4; i++) {
                a1[i] = sHo[(ty*4 + i)*132 + k0 + kk];
                a2[i] = sXs[(ty*4 + i)*132 + k0 + kk];
            }
#pragma unroll
            for (int j = 0; j < 8; j++) {
                b1[j] = sWu[kk*128 + tx + 16*j];
                b2[j] = sWx[kk*128 + tx + 16*j];
            }
#pragma unroll
            for (int i = 0; i < 4; i++)
#pragma unroll
                for (int j = 0; j < 8; j++)
                    acc[i][j] += a1[i] * b1[j] + a2[i] * b2[j];
        }
        __syncthreads();
    }
#pragma unroll
    for (int i = 0; i < 4; i++)
#pragma unroll
        for (int j = 0; j < 8; j++) {
            int r = ty*4 + i, c = tx + 16*j;
            float ho = sHo[r*132 + c];
            float xs = sXs[r*132 + c];
            float zl = acc[i][j] + bu[c] + bx[c] + ub[c];
            float z = 1.f / (1.f + expf(-zl));
            out[(size_t)(row0 + r) * Dv + c] = ho * z + xs * (1.f - z);
        }
}

// ---------------------------------------------------------------------------
extern "C" void kernel_launch(void* const* d_in, const int* in_sizes, int n_in,
                              void* d_out, int out_size)
{
    const float* X      = (const float*)d_in[0];
    const float* A      = (const float*)d_in[1];
    const float* Wk     = (const float*)d_in[2];
    const float* bias   = (const float*)d_in[3];
    const float* ub     = (const float*)d_in[4];
    const float* attn   = (const float*)d_in[5];
    const float* Wskip  = (const float*)d_in[6];
    const float* bskip  = (const float*)d_in[7];
    const float* Wu     = (const float*)d_in[8];
    const float* bu     = (const float*)d_in[9];
    const float* Wx     = (const float*)d_in[10];
    const float* bx     = (const float*)d_in[11];
    float* out = (float*)d_out;

    const int SM1 = (64*68 + 2*64*128) * 4;
    const int SM2 = (64*SB + 64*SA) * 4;
    const int SM3 = (64*SB + 64*SA) * 4;
    const int SM4 = (4*64*WQ + 64*WQ + 128*WT + 64*WT + 64*68) * 4;
    const int SM5 = (2*64*132 + 2*64*128) * 4;
    cudaFuncSetAttribute(proj_kernel,      cudaFuncAttributeMaxDynamicSharedMemorySize, SM1);
    cudaFuncSetAttribute(aggr_mma_kernel,  cudaFuncAttributeMaxDynamicSharedMemorySize, SM2);
    cudaFuncSetAttribute(q_mma_kernel,     cudaFuncAttributeMaxDynamicSharedMemorySize, SM3);
    cudaFuncSetAttribute(attn_bf16_kernel, cudaFuncAttributeMaxDynamicSharedMemorySize, SM4);
    cudaFuncSetAttribute(gate_kernel,      cudaFuncAttributeMaxDynamicSharedMemorySize, SM5);

    proj_kernel     <<<(Bv*Nv)/64, 256, SM1>>>(X, Wk, bias, Wskip, bskip);
    aggr_mma_kernel <<<dim3(Nv/64, Bv),     256, SM2>>>(A);
    q_mma_kernel    <<<dim3(Nv/64, Bv, Hv), 256, SM3>>>(attn);
    attn_bf16_kernel<<<dim3(Nv/64, Bv),     256, SM4>>>(A);
    gate_kernel     <<<(Bv*Nv)/64, 256, SM5>>>(Wu, bu, Wx, bx, ub, out);

    // Second tuple element: copy A into the tail of the output buffer.
    cudaMemcpyAsync(out + (size_t)Bv*Nv*Dv, A,
                    (size_t)Bv*Nv*Nv * sizeof(float),
                    cudaMemcpyDeviceToDevice);
}

// round 5
// speedup vs baseline: 4.5238x; 1.0757x over previous
#include <cuda_runtime.h>
#include <cuda_bf16.h>
#include <math.h>
#include <stdint.h>

#define Bv 4
#define Nv 2048
#define Fv 256
#define Dv 128
#define Hv 4

// Scratch (device globals per harness rules)
__device__ float g_Xs  [Bv*Nv*Dv];             // X@W_skip + b_skip (f32)
__device__ float g_Hout[Bv*Nv*Dv];             // relu(mean_h heads) (f32)
__device__ __nv_bfloat16 g_Hx0T[Bv*Dv*Nv];     // (X@kernel+bias)^T bf16 [b][d][n]
__device__ __nv_bfloat16 g_Hxb [Bv*Nv*Dv];     // Hx bf16 [b][n][d]
__device__ __nv_bfloat16 g_HxT [Bv*Dv*Nv];     // Hx bf16 [b][d][n]
__device__ __nv_bfloat16 g_Qb  [Hv*Bv*Nv*Dv];  // Q  bf16 [h][b][n][d]
__device__ __nv_bfloat16 g_attnT[Hv*Dv*Dv];    // attn^T bf16 [h][e][d]

// ---------------------------------------------------------------------------
// helpers
// ---------------------------------------------------------------------------
__device__ __forceinline__ float tanh_fast(float x) {
    float y; asm("tanh.approx.f32 %0, %1;" : "=f"(y) : "f"(x)); return y;
}
__device__ __forceinline__ unsigned pack_bf16(float lo, float hi) {
    unsigned d; asm("cvt.rn.bf16x2.f32 %0, %1, %2;" : "=r"(d) : "f"(hi), "f"(lo)); return d;
}
__device__ __forceinline__ void mma_bf16(float c[4], const unsigned a[4], const unsigned b[2]) {
    asm volatile(
        "mma.sync.aligned.m16n8k16.row.col.f32.bf16.bf16.f32 "
        "{%0,%1,%2,%3}, {%4,%5,%6,%7}, {%8,%9}, {%0,%1,%2,%3};"
        : "+f"(c[0]), "+f"(c[1]), "+f"(c[2]), "+f"(c[3])
        : "r"(a[0]), "r"(a[1]), "r"(a[2]), "r"(a[3]), "r"(b[0]), "r"(b[1]));
}
__device__ __forceinline__ void ldsm4(unsigned d[4], const unsigned* p) {
    unsigned addr = (unsigned)__cvta_generic_to_shared(p);
    asm volatile("ldmatrix.sync.aligned.m8n8.x4.shared.b16 {%0,%1,%2,%3}, [%4];"
        : "=r"(d[0]), "=r"(d[1]), "=r"(d[2]), "=r"(d[3]) : "r"(addr));
}
// A-fragment (16 rows x 16k) lane offset within array of word-stride S:
//   row = (lane&15), kword += (lane>>4)*4
#define AOFF(S) (((lane) & 15) * (S) + (((lane) >> 4) << 2))
// B two-octet (16 n-rows x 16k) lane offset:
//   lanes 0-7: r, kw | 8-15: r, kw+4 | 16-23: r+8, kw | 24-31: r+8, kw+4
#define BOFF(S) ((((lane) & 7) + (((lane) >> 4) << 3)) * (S) + ((((lane) >> 3) & 1) << 2))

// word strides (== 4 mod 32 -> conflict-free 8-row ldmatrix phases)
#define WQ 68   // 64 k-words + 4 pad
#define WT 36   // 32 k-words + 4 pad

// ---------------------------------------------------------------------------
// K0: attnT[h][e][d-words] = pack(attn[h][2dw][e], attn[h][2dw+1][e])
// ---------------------------------------------------------------------------
__global__ __launch_bounds__(256) void prep_attnT(const float* __restrict__ attn)
{
    int idx = blockIdx.x * 256 + threadIdx.x;       // 4*128*64 = 32768 words
    int h = idx >> 13, e = (idx >> 6) & 127, dw = idx & 63;
    const float* src = attn + (size_t)h * Dv * Dv;
    ((unsigned*)g_attnT)[idx] =
        pack_bf16(src[(2*dw) * Dv + e], src[(2*dw + 1) * Dv + e]);
}

// ---------------------------------------------------------------------------
// K1: Hx0T = bf16(X@kernel + bias)^T   and   Xs = X@W_skip + b_skip (f32)
// ---------------------------------------------------------------------------
__global__ __launch_bounds__(256) void proj_kernel(
    const float* __restrict__ X, const float* __restrict__ Wk,
    const float* __restrict__ bias, const float* __restrict__ Ws,
    const float* __restrict__ bskip)
{
    extern __shared__ float sm[];
    float* sX = sm;             // [64][68]
    float* sK = sX + 64*68;     // [64][128]
    float* sW = sK + 64*128;    // [64][128]
    const int tid = threadIdx.x, ty = tid >> 4, tx = tid & 15;
    const int row0 = blockIdx.x * 64;

    float acc1[4][8], acc2[4][8];
#pragma unroll
    for (int i = 0; i < 4; i++)
#pragma unroll
        for (int j = 0; j < 8; j++) { acc1[i][j] = 0.f; acc2[i][j] = 0.f; }

    for (int k0 = 0; k0 < Fv; k0 += 64) {
#pragma unroll
        for (int s = 0; s < 16; s++) {
            int idx = tid + 256 * s; int r = idx >> 6, c = idx & 63;
            sX[r*68 + c] = X[(size_t)(row0 + r) * Fv + k0 + c];
        }
#pragma unroll
        for (int s = 0; s < 8; s++) {
            int idx4 = tid + 256 * s; int r = idx4 >> 5, c4 = (idx4 & 31) * 4;
            *(float4*)&sK[r*128 + c4] = *(const float4*)&Wk[(size_t)(k0 + r) * Dv + c4];
            *(float4*)&sW[r*128 + c4] = *(const float4*)&Ws[(size_t)(k0 + r) * Dv + c4];
        }
        __syncthreads();
#pragma unroll 8
        for (int kk = 0; kk < 64; kk++) {
            float a[4], b1[8], b2[8];
#pragma unroll
            for (int i = 0; i < 4; i++) a[i] = sX[(ty*4 + i)*68 + kk];
#pragma unroll
            for (int j = 0; j < 8; j++) {
                b1[j] = sK[kk*128 + tx + 16*j];
                b2[j] = sW[kk*128 + tx + 16*j];
            }
#pragma unroll
            for (int i = 0; i < 4; i++)
#pragma unroll
                for (int j = 0; j < 8; j++) {
                    acc1[i][j] += a[i] * b1[j];
                    acc2[i][j] += a[i] * b2[j];
                }
        }
        __syncthreads();
    }
#pragma unroll
    for (int i = 0; i < 4; i++)
#pragma unroll
        for (int j = 0; j < 8; j++) {
            int r = row0 + ty*4 + i, c = tx + 16*j;
            int bb_ = r >> 11, nn = r & (Nv - 1);
            g_Xs[(size_t)r * Dv + c] = acc2[i][j] + bskip[c];
            g_Hx0T[((size_t)bb_ * Dv + c) * Nv + nn] =
                __float2bfloat16(acc1[i][j] + bias[c]);
        }
}

// ---------------------------------------------------------------------------
// K2: Hx = A @ Hx0  (bf16 mma + ldmatrix). grid(32,B), 256 thr.
// Warps (2n x 2d x 2k): warp tile 32n x 64d, k-half 32 of each 64-chunk.
// Epilogue: bf16 packed [n][d] + bf16 transposed [d][n].
// ---------------------------------------------------------------------------
__global__ __launch_bounds__(256, 1) void aggr_bf16_kernel(const float* __restrict__ A)
{
    extern __shared__ unsigned smw[];
    unsigned* sA = smw;          // [64][36]  A tile bf16 words [n][kw]
    unsigned* sB = smw + 64*36;  // [128][36] Hx0T chunk [d][kw]
    const int tid = threadIdx.x, warp = tid >> 5, lane = tid & 31;
    const int lr = lane >> 2, lc = lane & 3;
    const int an = warp & 1, ad = (warp >> 1) & 1, ak = warp >> 2;
    const int b = blockIdx.y, n0 = blockIdx.x * 64;
    const float* Ab = A + (size_t)b * Nv * Nv;
    const unsigned* HtW0 = (const unsigned*)g_Hx0T + (size_t)b * Dv * (Nv/2);
    const int aoff = AOFF(36), boff = BOFF(36);

    float acc[2][8][4];
#pragma unroll
    for (int f = 0; f < 2; f++)
#pragma unroll
        for (int j = 0; j < 8; j++)
#pragma unroll
            for (int i = 0; i < 4; i++) acc[f][j][i] = 0.f;

    for (int kt = 0; kt < Nv/64; kt++) {
        const int k0 = kt * 64;
#pragma unroll
        for (int s = 0; s < 8; s++) {      // A tile: 64 x 32 words
            int i = tid + 256*s; int r = i >> 5, w = i & 31;
            float2 v = *(const float2*)&Ab[(size_t)(n0 + r)*Nv + k0 + 2*w];
            sA[r*36 + w] = pack_bf16(v.x, v.y);
        }
#pragma unroll
        for (int s = 0; s < 4; s++) {      // Hx0T chunk: 128 x 32 words
            int i4 = tid + 256*s; int d = i4 >> 3, c4 = (i4 & 7) << 2;
            *(uint4*)&sB[d*36 + c4] =
                *(const uint4*)&HtW0[(size_t)d*(Nv/2) + (k0 >> 1) + c4];
        }
        __syncthreads();
#pragma unroll
        for (int ks = 0; ks < 2; ks++) {
            int kw = ak*16 + ks*8;
            unsigned a0[4], a1[4], bb[4];
            ldsm4(a0, sA + (an*32     )*36 + aoff + kw);
            ldsm4(a1, sA + (an*32 + 16)*36 + aoff + kw);
#pragma unroll
            for (int p = 0; p < 4; p++) {
                ldsm4(bb, sB + (ad*64 + p*16)*36 + boff + kw);
                mma_bf16(acc[0][2*p    ], a0, bb    );
                mma_bf16(acc[0][2*p + 1], a0, bb + 2);
                mma_bf16(acc[1][2*p    ], a1, bb    );
                mma_bf16(acc[1][2*p + 1], a1, bb + 2);
            }
        }
        __syncthreads();
    }
    // reduce k-halves (warp w with w+4) via smem
    float* red = (float*)smw;
    if (ak == 1) {
        int base = (((warp - 4) * 32) + lane) * 64;
#pragma unroll
        for (int f = 0; f < 2; f++)
#pragma unroll
            for (int j = 0; j < 8; j++)
#pragma unroll
                for (int i = 0; i < 4; i++)
                    red[base + f*32 + j*4 + i] = acc[f][j][i];
    }
    __syncthreads();
    if (ak == 0) {
        int base = ((warp * 32) + lane) * 64;
        unsigned* Pb = (unsigned*)g_Hxb;
        __nv_bfloat16* Tb = g_HxT + (size_t)b * Dv * Nv;
#pragma unroll
        for (int f = 0; f < 2; f++)
#pragma unroll
            for (int j = 0; j < 8; j++) {
                float v0 = acc[f][j][0] + red[base + f*32 + j*4 + 0];
                float v1 = acc[f][j][1] + red[base + f*32 + j*4 + 1];
                float v2 = acc[f][j][2] + red[base + f*32 + j*4 + 2];
                float v3 = acc[f][j][3] + red[base + f*32 + j*4 + 3];
                int n  = an*32 + f*16 + lr;
                int cc = ad*64 + j*8 + 2*lc;
                Pb[(((size_t)b*Nv + n0+n  )*Dv + cc) >> 1] = pack_bf16(v0, v1);
                Pb[(((size_t)b*Nv + n0+n+8)*Dv + cc) >> 1] = pack_bf16(v2, v3);
                Tb[(size_t)(cc  )*Nv + n0+n  ] = __float2bfloat16(v0);
                Tb[(size_t)(cc+1)*Nv + n0+n  ] = __float2bfloat16(v1);
                Tb[(size_t)(cc  )*Nv + n0+n+8] = __float2bfloat16(v2);
                Tb[(size_t)(cc+1)*Nv + n0+n+8] = __float2bfloat16(v3);
            }
    }
}

// ---------------------------------------------------------------------------
// K3: Q[h,b] = Hx[b] @ attn[h]  (bf16 mma + ldmatrix). grid(32,B,H).
// Warps (2n x 4e): warp tile 32n x 32e, full K=128.
// ---------------------------------------------------------------------------
__global__ __launch_bounds__(256, 1) void q_bf16_kernel()
{
    extern __shared__ unsigned smw[];
    unsigned* sHx = smw;            // [64][WQ]   Hx tile [n][kw]
    unsigned* sAt = smw + 64*WQ;    // [128][WQ]  attnT [e][kw]
    const int tid = threadIdx.x, warp = tid >> 5, lane = tid & 31;
    const int lr = lane >> 2, lc = lane & 3;
    const int qn = warp & 1, qd = warp >> 1;     // qd 0..3
    const int b = blockIdx.y, h = blockIdx.z, n0 = blockIdx.x * 64;
    const unsigned* HbW = (const unsigned*)g_Hxb + (size_t)b * Nv * (Dv/2);
    const unsigned* ATW = (const unsigned*)g_attnT + (size_t)h * Dv * (Dv/2);
    const int aoff = AOFF(WQ), boff = BOFF(WQ);

#pragma unroll
    for (int s = 0; s < 4; s++) {       // Hx tile: 64 x 64 words
        int i4 = tid + 256*s; int r = i4 >> 4, c4 = (i4 & 15) << 2;
        *(uint4*)&sHx[r*WQ + c4] = *(const uint4*)&HbW[(size_t)(n0 + r)*(Dv/2) + c4];
    }
#pragma unroll
    for (int s = 0; s < 8; s++) {       // attnT: 128 x 64 words
        int i4 = tid + 256*s; int e = i4 >> 4, c4 = (i4 & 15) << 2;
        *(uint4*)&sAt[e*WQ + c4] = *(const uint4*)&ATW[(size_t)e*(Dv/2) + c4];
    }
    __syncthreads();

    float acc[2][4][4];
#pragma unroll
    for (int f = 0; f < 2; f++)
#pragma unroll
        for (int j = 0; j < 4; j++)
#pragma unroll
            for (int i = 0; i < 4; i++) acc[f][j][i] = 0.f;

#pragma unroll
    for (int ks = 0; ks < 8; ks++) {
        unsigned a0[4], a1[4], bb[4];
        ldsm4(a0, sHx + (qn*32     )*WQ + aoff + 8*ks);
        ldsm4(a1, sHx + (qn*32 + 16)*WQ + aoff + 8*ks);
#pragma unroll
        for (int p = 0; p < 2; p++) {
            ldsm4(bb, sAt + (qd*32 + p*16)*WQ + boff + 8*ks);
            mma_bf16(acc[0][2*p    ], a0, bb    );
            mma_bf16(acc[0][2*p + 1], a0, bb + 2);
            mma_bf16(acc[1][2*p    ], a1, bb    );
            mma_bf16(acc[1][2*p + 1], a1, bb + 2);
        }
    }
    unsigned* Ob = (unsigned*)g_Qb;
#pragma unroll
    for (int f = 0; f < 2; f++)
#pragma unroll
        for (int j = 0; j < 4; j++) {
            int n = qn*32 + f*16 + lr, cc = qd*32 + j*8 + 2*lc;
            Ob[((((size_t)h*Bv + b)*Nv + n0+n  )*Dv + cc) >> 1] =
                pack_bf16(acc[f][j][0], acc[f][j][1]);
            Ob[((((size_t)h*Bv + b)*Nv + n0+n+8)*Dv + cc) >> 1] =
                pack_bf16(acc[f][j][2], acc[f][j][3]);
        }
}

// ---------------------------------------------------------------------------
// K4: fused attention, bf16 mma + ldmatrix. grid(32, B), 256 thr.
// GEMM1 warps (2n x 4m): 32n x 16m, full K=128.
// GEMM2 warps (2n x 2d x 2k): 32n x 64d, k-half 32m.
// ---------------------------------------------------------------------------
__global__ __launch_bounds__(256, 1) void attn_bf16_kernel(const float* __restrict__ A)
{
    extern __shared__ unsigned smw[];
    unsigned* sQ   = smw;                 // [4][64][WQ]
    unsigned* sHx  = sQ  + 4*64*WQ;       // [64][WQ]
    unsigned* sHxT = sHx + 64*WQ;         // [128][WT]
    unsigned* sAm  = sHxT + 128*WT;       // [64][WT]
    float*    sAr  = (float*)(sAm + 64*WT); // [64][68] raw A f32

    const int tid = threadIdx.x, warp = tid >> 5, lane = tid & 31;
    const int lr = lane >> 2, lc = lane & 3;
    const int g1n = warp & 1, g1m = (warp >> 1) & 3;
    const int g2n = warp & 1, g2d = (warp >> 1) & 1, g2k = warp >> 2;
    const int b = blockIdx.y, n0 = blockIdx.x * 64;
    const float* Ab = A + (size_t)b * Nv * Nv;
    const unsigned* HbW = (const unsigned*)g_Hxb + (size_t)b * Nv * (Dv/2);
    const unsigned* HtW = (const unsigned*)g_HxT + (size_t)b * Dv * (Nv/2);
    const int aoffQ = AOFF(WQ), boffQ = BOFF(WQ);
    const int aoffT = AOFF(WT), boffT = BOFF(WT);

    // ---- load Q (all 4 heads): 4*64*64 words
#pragma unroll
    for (int s = 0; s < 16; s++) {
        int i4 = tid + 256*s;
        int h = i4 >> 10, r = (i4 >> 4) & 63, c4 = (i4 & 15) * 4;
        const uint4* src = (const uint4*)((const unsigned*)g_Qb +
            (((size_t)h*Bv + b)*Nv + n0 + r) * (Dv/2));
        *(uint4*)&sQ[(h*64 + r)*WQ + c4] = src[c4 >> 2];
    }

    float acc[2][8][4];
#pragma unroll
    for (int f = 0; f < 2; f++)
#pragma unroll
        for (int j = 0; j < 8; j++)
#pragma unroll
            for (int i = 0; i < 4; i++) acc[f][j][i] = 0.f;

    for (int mt = 0; mt < Nv/64; mt++) {
        const int m0 = mt * 64;
#pragma unroll
        for (int s = 0; s < 4; s++) {       // sHx: 64 x 64 words
            int i4 = tid + 256*s; int r = i4 >> 4, c4 = (i4 & 15) * 4;
            *(uint4*)&sHx[r*WQ + c4] = *(const uint4*)&HbW[(size_t)(m0 + r)*(Dv/2) + c4];
        }
#pragma unroll
        for (int s = 0; s < 4; s++) {       // sHxT: 128 x 32 words
            int i4 = tid + 256*s; int d = i4 >> 3, c4 = (i4 & 7) * 4;
            *(uint4*)&sHxT[d*WT + c4] =
                *(const uint4*)&HtW[(size_t)d*(Nv/2) + (m0 >> 1) + c4];
        }
#pragma unroll
        for (int s = 0; s < 4; s++) {       // sAr: 64 x 64 f32
            int i4 = tid + 256*s; int r = i4 >> 4, c4 = (i4 & 15)*4;
            *(float4*)&sAr[r*68 + c4] =
                *(const float4*)&Ab[(size_t)(n0 + r)*Nv + m0 + c4];
        }
        __syncthreads();

        for (int h = 0; h < Hv; h++) {
            // ---- GEMM1: S(32n x 16m per warp) = Q_h . Hx^T
            float s4[2][2][4];
#pragma unroll
            for (int f = 0; f < 2; f++)
#pragma unroll
                for (int jm = 0; jm < 2; jm++)
#pragma unroll
                    for (int i = 0; i < 4; i++) s4[f][jm][i] = 0.f;
            const unsigned* q = sQ + (h*64 + g1n*32)*WQ;
#pragma unroll
            for (int ks = 0; ks < 8; ks++) {
                unsigned a0[4], a1[4], bb[4];
                ldsm4(a0, q +          aoffQ + 8*ks);
                ldsm4(a1, q + 16*WQ +  aoffQ + 8*ks);
                ldsm4(bb, sHx + (g1m*16)*WQ + boffQ + 8*ks);
                mma_bf16(s4[0][0], a0, bb    );
                mma_bf16(s4[0][1], a0, bb + 2);
                mma_bf16(s4[1][0], a1, bb    );
                mma_bf16(s4[1][1], a1, bb + 2);
            }
            // ---- Am = bf16(tanh(A * S))
#pragma unroll
            for (int f = 0; f < 2; f++)
#pragma unroll
                for (int jm = 0; jm < 2; jm++) {
                    int n  = g1n*32 + f*16 + lr;
                    int mm = g1m*16 + jm*8 + 2*lc;
                    float2 a01 = *(const float2*)&sAr[ n    *68 + mm];
                    float2 a23 = *(const float2*)&sAr[(n+8) *68 + mm];
                    sAm[ n    *WT + (mm >> 1)] =
                        pack_bf16(tanh_fast(a01.x * s4[f][jm][0]),
                                  tanh_fast(a01.y * s4[f][jm][1]));
                    sAm[(n+8) *WT + (mm >> 1)] =
                        pack_bf16(tanh_fast(a23.x * s4[f][jm][2]),
                                  tanh_fast(a23.y * s4[f][jm][3]));
                }
            __syncthreads();
            // ---- GEMM2: acc(32n x 64d per warp, k-half) += Am . Hx
#pragma unroll
            for (int ks = 0; ks < 2; ks++) {
                int kw = g2k*16 + ks*8;
                unsigned a0[4], a1[4], bb[4];
                ldsm4(a0, sAm + (g2n*32     )*WT + aoffT + kw);
                ldsm4(a1, sAm + (g2n*32 + 16)*WT + aoffT + kw);
#pragma unroll
                for (int p = 0; p < 4; p++) {
                    ldsm4(bb, sHxT + (g2d*64 + p*16)*WT + boffT + kw);
                    mma_bf16(acc[0][2*p    ], a0, bb    );
                    mma_bf16(acc[0][2*p + 1], a0, bb + 2);
                    mma_bf16(acc[1][2*p    ], a1, bb    );
                    mma_bf16(acc[1][2*p + 1], a1, bb + 2);
                }
            }
            __syncthreads();
        }
    }

    // ---- reduce k-halves (warp w with w+4), then Hout
    float* red = (float*)sQ;
    if (g2k == 1) {
        int base = (((warp - 4) * 32) + lane) * 64;
#pragma unroll
        for (int f = 0; f < 2; f++)
#pragma unroll
            for (int j = 0; j < 8; j++)
#pragma unroll
                for (int i = 0; i < 4; i++)
                    red[base + f*32 + j*4 + i] = acc[f][j][i];
    }
    __syncthreads();
    if (g2k == 0) {
        int base = ((warp * 32) + lane) * 64;
        float* Ho = g_Hout + ((size_t)b*Nv + n0)*Dv;
#pragma unroll
        for (int f = 0; f < 2; f++)
#pragma unroll
            for (int j = 0; j < 8; j++) {
                float v0 = (acc[f][j][0] + red[base + f*32 + j*4 + 0]) * 0.25f;
                float v1 = (acc[f][j][1] + red[base + f*32 + j*4 + 1]) * 0.25f;
                float v2 = (acc[f][j][2] + red[base + f*32 + j*4 + 2]) * 0.25f;
                float v3 = (acc[f][j][3] + red[base + f*32 + j*4 + 3]) * 0.25f;
                int n  = g2n*32 + f*16 + lr;
                int cc = g2d*64 + j*8 + 2*lc;
                *(float2*)&Ho[(size_t)n    *Dv + cc] =
                    make_float2(fmaxf(v0, 0.f), fmaxf(v1, 0.f));
                *(float2*)&Ho[(size_t)(n+8)*Dv + cc] =
                    make_float2(fmaxf(v2, 0.f), fmaxf(v3, 0.f));
            }
    }
}

// ---------------------------------------------------------------------------
// K5: z = sigmoid(Hout@W_u + Xs@W_x + biases); out = Hout*z + Xs*(1-z)  (SIMT)
// ---------------------------------------------------------------------------
__global__ __launch_bounds__(256) void gate_kernel(
    const float* __restrict__ Wu, const float* __restrict__ bu,
    const float* __restrict__ Wx, const float* __restrict__ bx,
    const float* __restrict__ ub, float* __restrict__ out)
{
    extern __shared__ float sm[];
    float* sHo = sm;              // [64][132]
    float* sXs = sHo + 64*132;    // [64][132]
    float* sWu = sXs + 64*132;    // [64][128]
    float* sWx = sWu + 64*128;    // [64][128]
    const int tid = threadIdx.x, ty = tid >> 4, tx = tid & 15;
    const int row0 = blockIdx.x * 64;

#pragma unroll
    for (int s = 0; s < 8; s++) {
        int idx4 = tid + 256 * s; int r = idx4 >> 5, c4 = (idx4 & 31) * 4;
        *(float4*)&sHo[r*132 + c4] = *(const float4*)&g_Hout[(size_t)(row0 + r) * Dv + c4];
        *(float4*)&sXs[r*132 + c4] = *(const float4*)&g_Xs  [(size_t)(row0 + r) * Dv + c4];
    }

    float acc[4][8];
#pragma unroll
    for (int i = 0; i < 4; i++)
#pragma unroll
        for (int j = 0; j < 8; j++) acc[i][j] = 0.f;

    for (int k0 = 0; k0 < Dv; k0 += 64) {
#pragma unroll
        for (int s = 0; s < 8; s++) {
            int idx4 = tid + 256 * s; int r = idx4 >> 5, c4 = (idx4 & 31) * 4;
            *(float4*)&sWu[r*128 + c4] = *(const float4*)&Wu[(size_t)(k0 + r) * Dv + c4];
            *(float4*)&sWx[r*128 + c4] = *(const float4*)&Wx[(size_t)(k0 + r) * Dv + c4];
        }
        __syncthreads();
#pragma unroll 8
        for (int kk = 0; kk < 64; kk++) {
            float a1[4], a2[4], b1[8], b2[8];
#pragma unroll
            for (int i = 0; i < 4; i++) {
                a1[i] = sHo[(ty*4 + i)*132 + k0 + kk];
                a2[i] = sXs[(ty*4 + i)*132 + k0 + kk];
            }
#pragma unroll
            for (int j = 0; j < 8; j++) {
                b1[j] = sWu[kk*128 + tx + 16*j];
                b2[j] = sWx[kk*128 + tx + 16*j];
            }
#pragma unroll
            for (int i = 0; i < 4; i++)
#pragma unroll
                for (int j = 0; j < 8; j++)
                    acc[i][j] += a1[i] * b1[j] + a2[i] * b2[j];
        }
        __syncthreads();
    }
#pragma unroll
    for (int i = 0; i < 4; i++)
#pragma unroll
        for (int j = 0; j < 8; j++) {
            int r = ty*4 + i, c = tx + 16*j;
            float ho = sHo[r*132 + c];
            float xs = sXs[r*132 + c];
            float zl = acc[i][j] + bu[c] + bx[c] + ub[c];
            float z = 1.f / (1.f + expf(-zl));
            out[(size_t)(row0 + r) * Dv + c] = ho * z + xs * (1.f - z);
        }
}

// ---------------------------------------------------------------------------
extern "C" void kernel_launch(void* const* d_in, const int* in_sizes, int n_in,
                              void* d_out, int out_size)
{
    const float* X      = (const float*)d_in[0];
    const float* A      = (const float*)d_in[1];
    const float* Wk     = (const float*)d_in[2];
    const float* bias   = (const float*)d_in[3];
    const float* ub     = (const float*)d_in[4];
    const float* attn   = (const float*)d_in[5];
    const float* Wskip  = (const float*)d_in[6];
    const float* bskip  = (const float*)d_in[7];
    const float* Wu     = (const float*)d_in[8];
    const float* bu     = (const float*)d_in[9];
    const float* Wx     = (const float*)d_in[10];
    const float* bx     = (const float*)d_in[11];
    float* out = (float*)d_out;

    const int SM1 = (64*68 + 2*64*128) * 4;
    const int SM2 = 8192 * 4;                       // max(load 6912, reduce 8192) words
    const int SM3 = (64*WQ + 128*WQ) * 4;
    const int SM4 = (4*64*WQ + 64*WQ + 128*WT + 64*WT + 64*68) * 4;
    const int SM5 = (2*64*132 + 2*64*128) * 4;
    cudaFuncSetAttribute(proj_kernel,      cudaFuncAttributeMaxDynamicSharedMemorySize, SM1);
    cudaFuncSetAttribute(aggr_bf16_kernel, cudaFuncAttributeMaxDynamicSharedMemorySize, SM2);
    cudaFuncSetAttribute(q_bf16_kernel,    cudaFuncAttributeMaxDynamicSharedMemorySize, SM3);
    cudaFuncSetAttribute(attn_bf16_kernel, cudaFuncAttributeMaxDynamicSharedMemorySize, SM4);
    cudaFuncSetAttribute(gate_kernel,      cudaFuncAttributeMaxDynamicSharedMemorySize, SM5);

    prep_attnT      <<<128, 256>>>(attn);
    proj_kernel     <<<(Bv*Nv)/64, 256, SM1>>>(X, Wk, bias, Wskip, bskip);
    aggr_bf16_kernel<<<dim3(Nv/64, Bv),     256, SM2>>>(A);
    q_bf16_kernel   <<<dim3(Nv/64, Bv, Hv), 256, SM3>>>();
    attn_bf16_kernel<<<dim3(Nv/64, Bv),     256, SM4>>>(A);
    gate_kernel     <<<(Bv*Nv)/64, 256, SM5>>>(Wu, bu, Wx, bx, ub, out);

    // Second tuple element: copy A into the tail of the output buffer.
    cudaMemcpyAsync(out + (size_t)Bv*Nv*Dv, A,
                    (size_t)Bv*Nv*Nv * sizeof(float),
                    cudaMemcpyDeviceToDevice);
}

// round 6
// speedup vs baseline: 5.6723x; 1.2539x over previous
#include <cuda_runtime.h>
#include <cuda_bf16.h>
#include <math.h>
#include <stdint.h>

#define Bv 4
#define Nv 2048
#define Fv 256
#define Dv 128
#define Hv 4

// Scratch (device globals per harness rules)
__device__ float g_Xs  [Bv*Nv*Dv];             // X@W_skip + b_skip (f32)
__device__ float g_Hout[Bv*Nv*Dv];             // relu(mean_h heads) (f32)
__device__ __nv_bfloat16 g_Hx0T[Bv*Dv*Nv];     // (X@kernel+bias)^T bf16 [b][d][n]
__device__ __nv_bfloat16 g_Hxb [Bv*Nv*Dv];     // Hx bf16 [b][n][d]
__device__ __nv_bfloat16 g_HxT [Bv*Dv*Nv];     // Hx bf16 [b][d][n]
__device__ __nv_bfloat16 g_Qb  [Hv*Bv*Nv*Dv];  // Q  bf16 [h][b][n][d]
__device__ __nv_bfloat16 g_attnT[Hv*Dv*Dv];    // attn^T bf16 [h][e][d]

// ---------------------------------------------------------------------------
// helpers
// ---------------------------------------------------------------------------
__device__ __forceinline__ float tanh_fast(float x) {
    float y; asm("tanh.approx.f32 %0, %1;" : "=f"(y) : "f"(x)); return y;
}
__device__ __forceinline__ unsigned pack_bf16(float lo, float hi) {
    unsigned d; asm("cvt.rn.bf16x2.f32 %0, %1, %2;" : "=r"(d) : "f"(hi), "f"(lo)); return d;
}
__device__ __forceinline__ void mma_bf16(float c[4], const unsigned a[4], const unsigned b[2]) {
    asm volatile(
        "mma.sync.aligned.m16n8k16.row.col.f32.bf16.bf16.f32 "
        "{%0,%1,%2,%3}, {%4,%5,%6,%7}, {%8,%9}, {%0,%1,%2,%3};"
        : "+f"(c[0]), "+f"(c[1]), "+f"(c[2]), "+f"(c[3])
        : "r"(a[0]), "r"(a[1]), "r"(a[2]), "r"(a[3]), "r"(b[0]), "r"(b[1]));
}
__device__ __forceinline__ void ldsm4(unsigned d[4], const unsigned* p) {
    unsigned addr = (unsigned)__cvta_generic_to_shared(p);
    asm volatile("ldmatrix.sync.aligned.m8n8.x4.shared.b16 {%0,%1,%2,%3}, [%4];"
        : "=r"(d[0]), "=r"(d[1]), "=r"(d[2]), "=r"(d[3]) : "r"(addr));
}
// A-fragment (16 rows x 16k) lane offset within array of word-stride S
#define AOFF(S) (((lane) & 15) * (S) + (((lane) >> 4) << 2))
// B two-octet (16 n-rows x 16k) lane offset
#define BOFF(S) ((((lane) & 7) + (((lane) >> 4) << 3)) * (S) + ((((lane) >> 3) & 1) << 2))

// word strides (== 4 mod 32 -> conflict-free 8-row ldmatrix phases)
#define WQ 68   // 64 k-words + 4 pad
#define WT 36   // 32 k-words + 4 pad

// ---------------------------------------------------------------------------
// K0: attnT[h][e][d-words] = pack(attn[h][2dw][e], attn[h][2dw+1][e])
// ---------------------------------------------------------------------------
__global__ __launch_bounds__(256) void prep_attnT(const float* __restrict__ attn)
{
    int idx = blockIdx.x * 256 + threadIdx.x;       // 4*128*64 = 32768 words
    int h = idx >> 13, e = (idx >> 6) & 127, dw = idx & 63;
    const float* src = attn + (size_t)h * Dv * Dv;
    ((unsigned*)g_attnT)[idx] =
        pack_bf16(src[(2*dw) * Dv + e], src[(2*dw + 1) * Dv + e]);
}

// ---------------------------------------------------------------------------
// K1: Hx0T = bf16(X@kernel + bias)^T   and   Xs = X@W_skip + b_skip (f32)
// ---------------------------------------------------------------------------
__global__ __launch_bounds__(256) void proj_kernel(
    const float* __restrict__ X, const float* __restrict__ Wk,
    const float* __restrict__ bias, const float* __restrict__ Ws,
    const float* __restrict__ bskip)
{
    extern __shared__ float sm[];
    float* sX = sm;             // [64][68]
    float* sK = sX + 64*68;     // [64][128]
    float* sW = sK + 64*128;    // [64][128]
    const int tid = threadIdx.x, ty = tid >> 4, tx = tid & 15;
    const int row0 = blockIdx.x * 64;

    float acc1[4][8], acc2[4][8];
#pragma unroll
    for (int i = 0; i < 4; i++)
#pragma unroll
        for (int j = 0; j < 8; j++) { acc1[i][j] = 0.f; acc2[i][j] = 0.f; }

    for (int k0 = 0; k0 < Fv; k0 += 64) {
#pragma unroll
        for (int s = 0; s < 16; s++) {
            int idx = tid + 256 * s; int r = idx >> 6, c = idx & 63;
            sX[r*68 + c] = X[(size_t)(row0 + r) * Fv + k0 + c];
        }
#pragma unroll
        for (int s = 0; s < 8; s++) {
            int idx4 = tid + 256 * s; int r = idx4 >> 5, c4 = (idx4 & 31) * 4;
            *(float4*)&sK[r*128 + c4] = *(const float4*)&Wk[(size_t)(k0 + r) * Dv + c4];
            *(float4*)&sW[r*128 + c4] = *(const float4*)&Ws[(size_t)(k0 + r) * Dv + c4];
        }
        __syncthreads();
#pragma unroll 8
        for (int kk = 0; kk < 64; kk++) {
            float a[4], b1[8], b2[8];
#pragma unroll
            for (int i = 0; i < 4; i++) a[i] = sX[(ty*4 + i)*68 + kk];
#pragma unroll
            for (int j = 0; j < 8; j++) {
                b1[j] = sK[kk*128 + tx + 16*j];
                b2[j] = sW[kk*128 + tx + 16*j];
            }
#pragma unroll
            for (int i = 0; i < 4; i++)
#pragma unroll
                for (int j = 0; j < 8; j++) {
                    acc1[i][j] += a[i] * b1[j];
                    acc2[i][j] += a[i] * b2[j];
                }
        }
        __syncthreads();
    }
#pragma unroll
    for (int i = 0; i < 4; i++)
#pragma unroll
        for (int j = 0; j < 8; j++) {
            int r = row0 + ty*4 + i, c = tx + 16*j;
            int bb_ = r >> 11, nn = r & (Nv - 1);
            g_Xs[(size_t)r * Dv + c] = acc2[i][j] + bskip[c];
            g_Hx0T[((size_t)bb_ * Dv + c) * Nv + nn] =
                __float2bfloat16(acc1[i][j] + bias[c]);
        }
}

// ---------------------------------------------------------------------------
// K2: Hx = A @ Hx0  (bf16 mma + ldmatrix). grid(32,B), 256 thr.
// Also streams the raw A tiles to the output tail (replaces cudaMemcpy).
// ---------------------------------------------------------------------------
__global__ __launch_bounds__(256, 1) void aggr_bf16_kernel(
    const float* __restrict__ A, float* __restrict__ outA)
{
    extern __shared__ unsigned smw[];
    unsigned* sA = smw;          // [64][36]  A tile bf16 words [n][kw]
    unsigned* sB = smw + 64*36;  // [128][36] Hx0T chunk [d][kw]
    const int tid = threadIdx.x, warp = tid >> 5, lane = tid & 31;
    const int lr = lane >> 2, lc = lane & 3;
    const int an = warp & 1, ad = (warp >> 1) & 1, ak = warp >> 2;
    const int b = blockIdx.y, n0 = blockIdx.x * 64;
    const float* Ab = A + (size_t)b * Nv * Nv;
    const unsigned* HtW0 = (const unsigned*)g_Hx0T + (size_t)b * Dv * (Nv/2);
    const int aoff = AOFF(36), boff = BOFF(36);

    float acc[2][8][4];
#pragma unroll
    for (int f = 0; f < 2; f++)
#pragma unroll
        for (int j = 0; j < 8; j++)
#pragma unroll
            for (int i = 0; i < 4; i++) acc[f][j][i] = 0.f;

    for (int kt = 0; kt < Nv/64; kt++) {
        const int k0 = kt * 64;
#pragma unroll
        for (int s = 0; s < 8; s++) {      // A tile: 64 x 32 words (+ out copy)
            int i = tid + 256*s; int r = i >> 5, w = i & 31;
            float2 v = *(const float2*)&Ab[(size_t)(n0 + r)*Nv + k0 + 2*w];
            sA[r*36 + w] = pack_bf16(v.x, v.y);
            *(float2*)&outA[((size_t)b*Nv + n0 + r)*Nv + k0 + 2*w] = v;
        }
#pragma unroll
        for (int s = 0; s < 4; s++) {      // Hx0T chunk: 128 x 32 words
            int i4 = tid + 256*s; int d = i4 >> 3, c4 = (i4 & 7) << 2;
            *(uint4*)&sB[d*36 + c4] =
                *(const uint4*)&HtW0[(size_t)d*(Nv/2) + (k0 >> 1) + c4];
        }
        __syncthreads();
#pragma unroll
        for (int ks = 0; ks < 2; ks++) {
            int kw = ak*16 + ks*8;
            unsigned a0[4], a1[4], bb[4];
            ldsm4(a0, sA + (an*32     )*36 + aoff + kw);
            ldsm4(a1, sA + (an*32 + 16)*36 + aoff + kw);
#pragma unroll
            for (int p = 0; p < 4; p++) {
                ldsm4(bb, sB + (ad*64 + p*16)*36 + boff + kw);
                mma_bf16(acc[0][2*p    ], a0, bb    );
                mma_bf16(acc[0][2*p + 1], a0, bb + 2);
                mma_bf16(acc[1][2*p    ], a1, bb    );
                mma_bf16(acc[1][2*p + 1], a1, bb + 2);
            }
        }
        __syncthreads();
    }
    // reduce k-halves (warp w with w+4) via smem
    float* red = (float*)smw;
    if (ak == 1) {
        int base = (((warp - 4) * 32) + lane) * 64;
#pragma unroll
        for (int f = 0; f < 2; f++)
#pragma unroll
            for (int j = 0; j < 8; j++)
#pragma unroll
                for (int i = 0; i < 4; i++)
                    red[base + f*32 + j*4 + i] = acc[f][j][i];
    }
    __syncthreads();
    if (ak == 0) {
        int base = ((warp * 32) + lane) * 64;
        unsigned* Pb = (unsigned*)g_Hxb;
        __nv_bfloat16* Tb = g_HxT + (size_t)b * Dv * Nv;
#pragma unroll
        for (int f = 0; f < 2; f++)
#pragma unroll
            for (int j = 0; j < 8; j++) {
                float v0 = acc[f][j][0] + red[base + f*32 + j*4 + 0];
                float v1 = acc[f][j][1] + red[base + f*32 + j*4 + 1];
                float v2 = acc[f][j][2] + red[base + f*32 + j*4 + 2];
                float v3 = acc[f][j][3] + red[base + f*32 + j*4 + 3];
                int n  = an*32 + f*16 + lr;
                int cc = ad*64 + j*8 + 2*lc;
                Pb[(((size_t)b*Nv + n0+n  )*Dv + cc) >> 1] = pack_bf16(v0, v1);
                Pb[(((size_t)b*Nv + n0+n+8)*Dv + cc) >> 1] = pack_bf16(v2, v3);
                Tb[(size_t)(cc  )*Nv + n0+n  ] = __float2bfloat16(v0);
                Tb[(size_t)(cc+1)*Nv + n0+n  ] = __float2bfloat16(v1);
                Tb[(size_t)(cc  )*Nv + n0+n+8] = __float2bfloat16(v2);
                Tb[(size_t)(cc+1)*Nv + n0+n+8] = __float2bfloat16(v3);
            }
    }
}

// ---------------------------------------------------------------------------
// K3: Q[h,b] = Hx[b] @ attn[h]  (bf16 mma + ldmatrix). grid(32,B,H).
// ---------------------------------------------------------------------------
__global__ __launch_bounds__(256, 1) void q_bf16_kernel()
{
    extern __shared__ unsigned smw[];
    unsigned* sHx = smw;            // [64][WQ]   Hx tile [n][kw]
    unsigned* sAt = smw + 64*WQ;    // [128][WQ]  attnT [e][kw]
    const int tid = threadIdx.x, warp = tid >> 5, lane = tid & 31;
    const int lr = lane >> 2, lc = lane & 3;
    const int qn = warp & 1, qd = warp >> 1;     // qd 0..3
    const int b = blockIdx.y, h = blockIdx.z, n0 = blockIdx.x * 64;
    const unsigned* HbW = (const unsigned*)g_Hxb + (size_t)b * Nv * (Dv/2);
    const unsigned* ATW = (const unsigned*)g_attnT + (size_t)h * Dv * (Dv/2);
    const int aoff = AOFF(WQ), boff = BOFF(WQ);

#pragma unroll
    for (int s = 0; s < 4; s++) {       // Hx tile: 64 x 64 words
        int i4 = tid + 256*s; int r = i4 >> 4, c4 = (i4 & 15) << 2;
        *(uint4*)&sHx[r*WQ + c4] = *(const uint4*)&HbW[(size_t)(n0 + r)*(Dv/2) + c4];
    }
#pragma unroll
    for (int s = 0; s < 8; s++) {       // attnT: 128 x 64 words
        int i4 = tid + 256*s; int e = i4 >> 4, c4 = (i4 & 15) << 2;
        *(uint4*)&sAt[e*WQ + c4] = *(const uint4*)&ATW[(size_t)e*(Dv/2) + c4];
    }
    __syncthreads();

    float acc[2][4][4];
#pragma unroll
    for (int f = 0; f < 2; f++)
#pragma unroll
        for (int j = 0; j < 4; j++)
#pragma unroll
            for (int i = 0; i < 4; i++) acc[f][j][i] = 0.f;

#pragma unroll
    for (int ks = 0; ks < 8; ks++) {
        unsigned a0[4], a1[4], bb[4];
        ldsm4(a0, sHx + (qn*32     )*WQ + aoff + 8*ks);
        ldsm4(a1, sHx + (qn*32 + 16)*WQ + aoff + 8*ks);
#pragma unroll
        for (int p = 0; p < 2; p++) {
            ldsm4(bb, sAt + (qd*32 + p*16)*WQ + boff + 8*ks);
            mma_bf16(acc[0][2*p    ], a0, bb    );
            mma_bf16(acc[0][2*p + 1], a0, bb + 2);
            mma_bf16(acc[1][2*p    ], a1, bb    );
            mma_bf16(acc[1][2*p + 1], a1, bb + 2);
        }
    }
    unsigned* Ob = (unsigned*)g_Qb;
#pragma unroll
    for (int f = 0; f < 2; f++)
#pragma unroll
        for (int j = 0; j < 4; j++) {
            int n = qn*32 + f*16 + lr, cc = qd*32 + j*8 + 2*lc;
            Ob[((((size_t)h*Bv + b)*Nv + n0+n  )*Dv + cc) >> 1] =
                pack_bf16(acc[f][j][0], acc[f][j][1]);
            Ob[((((size_t)h*Bv + b)*Nv + n0+n+8)*Dv + cc) >> 1] =
                pack_bf16(acc[f][j][2], acc[f][j][3]);
        }
}

// ---------------------------------------------------------------------------
// K4: fused attention with head-sum factorization.
// C[n,m] = sum_h tanh(A[n,m] * S_h[n,m])  (f32 register accumulation)
// acc   += C @ Hx   (single GEMM2 per m-tile instead of 4)
// GEMM1 warps (2n x 4m): 32n x 16m per h. GEMM2 warps (2n x 2d x 2k).
// ---------------------------------------------------------------------------
__global__ __launch_bounds__(256, 1) void attn_bf16_kernel(const float* __restrict__ A)
{
    extern __shared__ unsigned smw[];
    unsigned* sQ   = smw;                 // [4][64][WQ]
    unsigned* sHx  = sQ  + 4*64*WQ;       // [64][WQ]
    unsigned* sHxT = sHx + 64*WQ;         // [128][WT]
    unsigned* sAm  = sHxT + 128*WT;       // [64][WT]   packed C
    float*    sAr  = (float*)(sAm + 64*WT); // [64][68] raw A f32

    const int tid = threadIdx.x, warp = tid >> 5, lane = tid & 31;
    const int lr = lane >> 2, lc = lane & 3;
    const int g1n = warp & 1, g1m = (warp >> 1) & 3;
    const int g2n = warp & 1, g2d = (warp >> 1) & 1, g2k = warp >> 2;
    const int b = blockIdx.y, n0 = blockIdx.x * 64;
    const float* Ab = A + (size_t)b * Nv * Nv;
    const unsigned* HbW = (const unsigned*)g_Hxb + (size_t)b * Nv * (Dv/2);
    const unsigned* HtW = (const unsigned*)g_HxT + (size_t)b * Dv * (Nv/2);
    const int aoffQ = AOFF(WQ), boffQ = BOFF(WQ);
    const int aoffT = AOFF(WT), boffT = BOFF(WT);

    // ---- load Q (all 4 heads): 4*64*64 words
#pragma unroll
    for (int s = 0; s < 16; s++) {
        int i4 = tid + 256*s;
        int h = i4 >> 10, r = (i4 >> 4) & 63, c4 = (i4 & 15) * 4;
        const uint4* src = (const uint4*)((const unsigned*)g_Qb +
            (((size_t)h*Bv + b)*Nv + n0 + r) * (Dv/2));
        *(uint4*)&sQ[(h*64 + r)*WQ + c4] = src[c4 >> 2];
    }

    float acc[2][8][4];
#pragma unroll
    for (int f = 0; f < 2; f++)
#pragma unroll
        for (int j = 0; j < 8; j++)
#pragma unroll
            for (int i = 0; i < 4; i++) acc[f][j][i] = 0.f;

    for (int mt = 0; mt < Nv/64; mt++) {
        const int m0 = mt * 64;
#pragma unroll
        for (int s = 0; s < 4; s++) {       // sHx: 64 x 64 words
            int i4 = tid + 256*s; int r = i4 >> 4, c4 = (i4 & 15) * 4;
            *(uint4*)&sHx[r*WQ + c4] = *(const uint4*)&HbW[(size_t)(m0 + r)*(Dv/2) + c4];
        }
#pragma unroll
        for (int s = 0; s < 4; s++) {       // sHxT: 128 x 32 words
            int i4 = tid + 256*s; int d = i4 >> 3, c4 = (i4 & 7) * 4;
            *(uint4*)&sHxT[d*WT + c4] =
                *(const uint4*)&HtW[(size_t)d*(Nv/2) + (m0 >> 1) + c4];
        }
#pragma unroll
        for (int s = 0; s < 4; s++) {       // sAr: 64 x 64 f32
            int i4 = tid + 256*s; int r = i4 >> 4, c4 = (i4 & 15)*4;
            *(float4*)&sAr[r*68 + c4] =
                *(const float4*)&Ab[(size_t)(n0 + r)*Nv + m0 + c4];
        }
        __syncthreads();

        // hoist this warp's A values (reused across all 4 heads)
        float aA[2][2][4];
#pragma unroll
        for (int f = 0; f < 2; f++)
#pragma unroll
            for (int jm = 0; jm < 2; jm++) {
                int n  = g1n*32 + f*16 + lr;
                int mm = g1m*16 + jm*8 + 2*lc;
                float2 a01 = *(const float2*)&sAr[ n    *68 + mm];
                float2 a23 = *(const float2*)&sAr[(n+8) *68 + mm];
                aA[f][jm][0] = a01.x; aA[f][jm][1] = a01.y;
                aA[f][jm][2] = a23.x; aA[f][jm][3] = a23.y;
            }

        // C = sum_h tanh(A * S_h), accumulated in f32 registers
        float C[2][2][4];
#pragma unroll
        for (int f = 0; f < 2; f++)
#pragma unroll
            for (int jm = 0; jm < 2; jm++)
#pragma unroll
                for (int i = 0; i < 4; i++) C[f][jm][i] = 0.f;

#pragma unroll
        for (int h = 0; h < Hv; h++) {
            float s4[2][2][4];
#pragma unroll
            for (int f = 0; f < 2; f++)
#pragma unroll
                for (int jm = 0; jm < 2; jm++)
#pragma unroll
                    for (int i = 0; i < 4; i++) s4[f][jm][i] = 0.f;
            const unsigned* q = sQ + (h*64 + g1n*32)*WQ;
#pragma unroll
            for (int ks = 0; ks < 8; ks++) {
                unsigned a0[4], a1[4], bb[4];
                ldsm4(a0, q +         aoffQ + 8*ks);
                ldsm4(a1, q + 16*WQ + aoffQ + 8*ks);
                ldsm4(bb, sHx + (g1m*16)*WQ + boffQ + 8*ks);
                mma_bf16(s4[0][0], a0, bb    );
                mma_bf16(s4[0][1], a0, bb + 2);
                mma_bf16(s4[1][0], a1, bb    );
                mma_bf16(s4[1][1], a1, bb + 2);
            }
#pragma unroll
            for (int f = 0; f < 2; f++)
#pragma unroll
                for (int jm = 0; jm < 2; jm++)
#pragma unroll
                    for (int i = 0; i < 4; i++)
                        C[f][jm][i] += tanh_fast(aA[f][jm][i] * s4[f][jm][i]);
        }

        // pack C -> sAm (bf16)
#pragma unroll
        for (int f = 0; f < 2; f++)
#pragma unroll
            for (int jm = 0; jm < 2; jm++) {
                int n  = g1n*32 + f*16 + lr;
                int mm = g1m*16 + jm*8 + 2*lc;
                sAm[ n    *WT + (mm >> 1)] = pack_bf16(C[f][jm][0], C[f][jm][1]);
                sAm[(n+8) *WT + (mm >> 1)] = pack_bf16(C[f][jm][2], C[f][jm][3]);
            }
        __syncthreads();

        // ---- GEMM2 (once per m-tile): acc += C . Hx
#pragma unroll
        for (int ks = 0; ks < 2; ks++) {
            int kw = g2k*16 + ks*8;
            unsigned a0[4], a1[4], bb[4];
            ldsm4(a0, sAm + (g2n*32     )*WT + aoffT + kw);
            ldsm4(a1, sAm + (g2n*32 + 16)*WT + aoffT + kw);
#pragma unroll
            for (int p = 0; p < 4; p++) {
                ldsm4(bb, sHxT + (g2d*64 + p*16)*WT + boffT + kw);
                mma_bf16(acc[0][2*p    ], a0, bb    );
                mma_bf16(acc[0][2*p + 1], a0, bb + 2);
                mma_bf16(acc[1][2*p    ], a1, bb    );
                mma_bf16(acc[1][2*p + 1], a1, bb + 2);
            }
        }
        __syncthreads();
    }

    // ---- reduce k-halves (warp w with w+4), then Hout
    float* red = (float*)sQ;
    if (g2k == 1) {
        int base = (((warp - 4) * 32) + lane) * 64;
#pragma unroll
        for (int f = 0; f < 2; f++)
#pragma unroll
            for (int j = 0; j < 8; j++)
#pragma unroll
                for (int i = 0; i < 4; i++)
                    red[base + f*32 + j*4 + i] = acc[f][j][i];
    }
    __syncthreads();
    if (g2k == 0) {
        int base = ((warp * 32) + lane) * 64;
        float* Ho = g_Hout + ((size_t)b*Nv + n0)*Dv;
#pragma unroll
        for (int f = 0; f < 2; f++)
#pragma unroll
            for (int j = 0; j < 8; j++) {
                float v0 = (acc[f][j][0] + red[base + f*32 + j*4 + 0]) * 0.25f;
                float v1 = (acc[f][j][1] + red[base + f*32 + j*4 + 1]) * 0.25f;
                float v2 = (acc[f][j][2] + red[base + f*32 + j*4 + 2]) * 0.25f;
                float v3 = (acc[f][j][3] + red[base + f*32 + j*4 + 3]) * 0.25f;
                int n  = g2n*32 + f*16 + lr;
                int cc = g2d*64 + j*8 + 2*lc;
                *(float2*)&Ho[(size_t)n    *Dv + cc] =
                    make_float2(fmaxf(v0, 0.f), fmaxf(v1, 0.f));
                *(float2*)&Ho[(size_t)(n+8)*Dv + cc] =
                    make_float2(fmaxf(v2, 0.f), fmaxf(v3, 0.f));
            }
    }
}

// ---------------------------------------------------------------------------
// K5: z = sigmoid(Hout@W_u + Xs@W_x + biases); out = Hout*z + Xs*(1-z)  (SIMT)
// ---------------------------------------------------------------------------
__global__ __launch_bounds__(256) void gate_kernel(
    const float* __restrict__ Wu, const float* __restrict__ bu,
    const float* __restrict__ Wx, const float* __restrict__ bx,
    const float* __restrict__ ub, float* __restrict__ out)
{
    extern __shared__ float sm[];
    float* sHo = sm;              // [64][132]
    float* sXs = sHo + 64*132;    // [64][132]
    float* sWu = sXs + 64*132;    // [64][128]
    float* sWx = sWu + 64*128;    // [64][128]
    const int tid = threadIdx.x, ty = tid >> 4, tx = tid & 15;
    const int row0 = blockIdx.x * 64;

#pragma unroll
    for (int s = 0; s < 8; s++) {
        int idx4 = tid + 256 * s; int r = idx4 >> 5, c4 = (idx4 & 31) * 4;
        *(float4*)&sHo[r*132 + c4] = *(const float4*)&g_Hout[(size_t)(row0 + r) * Dv + c4];
        *(float4*)&sXs[r*132 + c4] = *(const float4*)&g_Xs  [(size_t)(row0 + r) * Dv + c4];
    }

    float acc[4][8];
#pragma unroll
    for (int i = 0; i < 4; i++)
#pragma unroll
        for (int j = 0; j < 8; j++) acc[i][j] = 0.f;

    for (int k0 = 0; k0 < Dv; k0 += 64) {
#pragma unroll
        for (int s = 0; s < 8; s++) {
            int idx4 = tid + 256 * s; int r = idx4 >> 5, c4 = (idx4 & 31) * 4;
            *(float4*)&sWu[r*128 + c4] = *(const float4*)&Wu[(size_t)(k0 + r) * Dv + c4];
            *(float4*)&sWx[r*128 + c4] = *(const float4*)&Wx[(size_t)(k0 + r) * Dv + c4];
        }
        __syncthreads();
#pragma unroll 8
        for (int kk = 0; kk < 64; kk++) {
            float a1[4], a2[4], b1[8], b2[8];
#pragma unroll
            for (int i = 0; i < 4; i++) {
                a1[i] = sHo[(ty*4 + i)*132 + k0 + kk];
                a2[i] = sXs[(ty*4 + i)*132 + k0 + kk];
            }
#pragma unroll
            for (int j = 0; j < 8; j++) {
                b1[j] = sWu[kk*128 + tx + 16*j];
                b2[j] = sWx[kk*128 + tx + 16*j];
            }
#pragma unroll
            for (int i = 0; i < 4; i++)
#pragma unroll
                for (int j = 0; j < 8; j++)
                    acc[i][j] += a1[i] * b1[j] + a2[i] * b2[j];
        }
        __syncthreads();
    }
#pragma unroll
    for (int i = 0; i < 4; i++)
#pragma unroll
        for (int j = 0; j < 8; j++) {
            int r = ty*4 + i, c = tx + 16*j;
            float ho = sHo[r*132 + c];
            float xs = sXs[r*132 + c];
            float zl = acc[i][j] + bu[c] + bx[c] + ub[c];
            float z = 1.f / (1.f + expf(-zl));
            out[(size_t)(row0 + r) * Dv + c] = ho * z + xs * (1.f - z);
        }
}

// ---------------------------------------------------------------------------
extern "C" void kernel_launch(void* const* d_in, const int* in_sizes, int n_in,
                              void* d_out, int out_size)
{
    const float* X      = (const float*)d_in[0];
    const float* A      = (const float*)d_in[1];
    const float* Wk     = (const float*)d_in[2];
    const float* bias   = (const float*)d_in[3];
    const float* ub     = (const float*)d_in[4];
    const float* attn   = (const float*)d_in[5];
    const float* Wskip  = (const float*)d_in[6];
    const float* bskip  = (const float*)d_in[7];
    const float* Wu     = (const float*)d_in[8];
    const float* bu     = (const float*)d_in[9];
    const float* Wx     = (const float*)d_in[10];
    const float* bx     = (const float*)d_in[11];
    float* out = (float*)d_out;

    const int SM1 = (64*68 + 2*64*128) * 4;
    const int SM2 = 8192 * 4;                       // max(load 6912, reduce 8192) words
    const int SM3 = (64*WQ + 128*WQ) * 4;
    const int SM4 = (4*64*WQ + 64*WQ + 128*WT + 64*WT + 64*68) * 4;
    const int SM5 = (2*64*132 + 2*64*128) * 4;
    cudaFuncSetAttribute(proj_kernel,      cudaFuncAttributeMaxDynamicSharedMemorySize, SM1);
    cudaFuncSetAttribute(aggr_bf16_kernel, cudaFuncAttributeMaxDynamicSharedMemorySize, SM2);
    cudaFuncSetAttribute(q_bf16_kernel,    cudaFuncAttributeMaxDynamicSharedMemorySize, SM3);
    cudaFuncSetAttribute(attn_bf16_kernel, cudaFuncAttributeMaxDynamicSharedMemorySize, SM4);
    cudaFuncSetAttribute(gate_kernel,      cudaFuncAttributeMaxDynamicSharedMemorySize, SM5);

    prep_attnT      <<<128, 256>>>(attn);
    proj_kernel     <<<(Bv*Nv)/64, 256, SM1>>>(X, Wk, bias, Wskip, bskip);
    aggr_bf16_kernel<<<dim3(Nv/64, Bv),     256, SM2>>>(A, out + (size_t)Bv*Nv*Dv);
    q_bf16_kernel   <<<dim3(Nv/64, Bv, Hv), 256, SM3>>>();
    attn_bf16_kernel<<<dim3(Nv/64, Bv),     256, SM4>>>(A);
    gate_kernel     <<<(Bv*Nv)/64, 256, SM5>>>(Wu, bu, Wx, bx, ub, out);
}

// round 8
// speedup vs baseline: 6.2664x; 1.1047x over previous
#include <cuda_runtime.h>
#include <cuda_bf16.h>
#include <math.h>
#include <stdint.h>

#define Bv 4
#define Nv 2048
#define Fv 256
#define Dv 128
#define Hv 4

// Scratch (device globals per harness rules)
__device__ float g_Xs  [Bv*Nv*Dv];             // X@W_skip + b_skip (f32)
__device__ float g_Hout[Bv*Nv*Dv];             // relu(mean_h heads) (f32)
__device__ __nv_bfloat16 g_Hx0T[Bv*Dv*Nv];     // (X@kernel+bias)^T bf16 [b][d][n]
__device__ __nv_bfloat16 g_Hxb [Bv*Nv*Dv];     // Hx bf16 [b][n][d]
__device__ __nv_bfloat16 g_HxT [Bv*Dv*Nv];     // Hx bf16 [b][d][n]
__device__ __nv_bfloat16 g_Qb  [Hv*Bv*Nv*Dv];  // Q  bf16 [h][b][n][d]
__device__ __nv_bfloat16 g_attnT[Hv*Dv*Dv];    // attn^T bf16 [h][e][d]

// ---------------------------------------------------------------------------
// helpers
// ---------------------------------------------------------------------------
__device__ __forceinline__ float tanh_fast(float x) {
    float y; asm("tanh.approx.f32 %0, %1;" : "=f"(y) : "f"(x)); return y;
}
__device__ __forceinline__ unsigned pack_bf16(float lo, float hi) {
    unsigned d; asm("cvt.rn.bf16x2.f32 %0, %1, %2;" : "=r"(d) : "f"(hi), "f"(lo)); return d;
}
__device__ __forceinline__ void mma_bf16(float c[4], const unsigned a[4], const unsigned b[2]) {
    asm volatile(
        "mma.sync.aligned.m16n8k16.row.col.f32.bf16.bf16.f32 "
        "{%0,%1,%2,%3}, {%4,%5,%6,%7}, {%8,%9}, {%0,%1,%2,%3};"
        : "+f"(c[0]), "+f"(c[1]), "+f"(c[2]), "+f"(c[3])
        : "r"(a[0]), "r"(a[1]), "r"(a[2]), "r"(a[3]), "r"(b[0]), "r"(b[1]));
}
__device__ __forceinline__ void ldsm4(unsigned d[4], const unsigned* p) {
    unsigned addr = (unsigned)__cvta_generic_to_shared(p);
    asm volatile("ldmatrix.sync.aligned.m8n8.x4.shared.b16 {%0,%1,%2,%3}, [%4];"
        : "=r"(d[0]), "=r"(d[1]), "=r"(d[2]), "=r"(d[3]) : "r"(addr));
}
__device__ __forceinline__ void cpa16(unsigned* dst, const void* src) {
    unsigned d = (unsigned)__cvta_generic_to_shared(dst);
    asm volatile("cp.async.cg.shared.global [%0], [%1], 16;" :: "r"(d), "l"(src));
}
// A-fragment (16 rows x 16k) lane offset within array of word-stride S
#define AOFF(S) (((lane) & 15) * (S) + (((lane) >> 4) << 2))
// B two-octet (16 n-rows x 16k) lane offset
#define BOFF(S) ((((lane) & 7) + (((lane) >> 4) << 3)) * (S) + ((((lane) >> 3) & 1) << 2))

// word strides (== 4 mod 32 -> conflict-free 8-row ldmatrix phases)
#define WQ 68   // 64 k-words + 4 pad
#define WT 36   // 32 k-words + 4 pad

// attn kernel smem plan (words): sQ | buf0 | buf1
#define TILE_W (64*WQ + 128*WT + 64*68)   // sHx + sHxT + sAr = 13312
#define SQ_W   (4*64*WQ)                  // 17408

// ---------------------------------------------------------------------------
// K0: attnT[h][e][d-words] = pack(attn[h][2dw][e], attn[h][2dw+1][e])
// ---------------------------------------------------------------------------
__global__ __launch_bounds__(256) void prep_attnT(const float* __restrict__ attn)
{
    int idx = blockIdx.x * 256 + threadIdx.x;       // 4*128*64 = 32768 words
    int h = idx >> 13, e = (idx >> 6) & 127, dw = idx & 63;
    const float* src = attn + (size_t)h * Dv * Dv;
    ((unsigned*)g_attnT)[idx] =
        pack_bf16(src[(2*dw) * Dv + e], src[(2*dw + 1) * Dv + e]);
}

// ---------------------------------------------------------------------------
// K1: Hx0T = bf16(X@kernel + bias)^T   and   Xs = X@W_skip + b_skip (f32)
// ---------------------------------------------------------------------------
__global__ __launch_bounds__(256) void proj_kernel(
    const float* __restrict__ X, const float* __restrict__ Wk,
    const float* __restrict__ bias, const float* __restrict__ Ws,
    const float* __restrict__ bskip)
{
    extern __shared__ float sm[];
    float* sX = sm;             // [64][68]
    float* sK = sX + 64*68;     // [64][128]
    float* sW = sK + 64*128;    // [64][128]
    const int tid = threadIdx.x, ty = tid >> 4, tx = tid & 15;
    const int row0 = blockIdx.x * 64;

    float acc1[4][8], acc2[4][8];
#pragma unroll
    for (int i = 0; i < 4; i++)
#pragma unroll
        for (int j = 0; j < 8; j++) { acc1[i][j] = 0.f; acc2[i][j] = 0.f; }

    for (int k0 = 0; k0 < Fv; k0 += 64) {
#pragma unroll
        for (int s = 0; s < 16; s++) {
            int idx = tid + 256 * s; int r = idx >> 6, c = idx & 63;
            sX[r*68 + c] = X[(size_t)(row0 + r) * Fv + k0 + c];
        }
#pragma unroll
        for (int s = 0; s < 8; s++) {
            int idx4 = tid + 256 * s; int r = idx4 >> 5, c4 = (idx4 & 31) * 4;
            *(float4*)&sK[r*128 + c4] = *(const float4*)&Wk[(size_t)(k0 + r) * Dv + c4];
            *(float4*)&sW[r*128 + c4] = *(const float4*)&Ws[(size_t)(k0 + r) * Dv + c4];
        }
        __syncthreads();
#pragma unroll 8
        for (int kk = 0; kk < 64; kk++) {
            float a[4], b1[8], b2[8];
#pragma unroll
            for (int i = 0; i < 4; i++) a[i] = sX[(ty*4 + i)*68 + kk];
#pragma unroll
            for (int j = 0; j < 8; j++) {
                b1[j] = sK[kk*128 + tx + 16*j];
                b2[j] = sW[kk*128 + tx + 16*j];
            }
#pragma unroll
            for (int i = 0; i < 4; i++)
#pragma unroll
                for (int j = 0; j < 8; j++) {
                    acc1[i][j] += a[i] * b1[j];
                    acc2[i][j] += a[i] * b2[j];
                }
        }
        __syncthreads();
    }
#pragma unroll
    for (int i = 0; i < 4; i++)
#pragma unroll
        for (int j = 0; j < 8; j++) {
            int r = row0 + ty*4 + i, c = tx + 16*j;
            int bb_ = r >> 11, nn = r & (Nv - 1);
            g_Xs[(size_t)r * Dv + c] = acc2[i][j] + bskip[c];
            g_Hx0T[((size_t)bb_ * Dv + c) * Nv + nn] =
                __float2bfloat16(acc1[i][j] + bias[c]);
        }
}

// ---------------------------------------------------------------------------
// K2: Hx = A @ Hx0  (bf16 mma + ldmatrix). grid(32,B), 256 thr.
// Also streams the raw A tiles to the output tail (replaces cudaMemcpy).
// ---------------------------------------------------------------------------
__global__ __launch_bounds__(256, 1) void aggr_bf16_kernel(
    const float* __restrict__ A, float* __restrict__ outA)
{
    extern __shared__ unsigned smw[];
    unsigned* sA = smw;          // [64][36]  A tile bf16 words [n][kw]
    unsigned* sB = smw + 64*36;  // [128][36] Hx0T chunk [d][kw]
    const int tid = threadIdx.x, warp = tid >> 5, lane = tid & 31;
    const int lr = lane >> 2, lc = lane & 3;
    const int an = warp & 1, ad = (warp >> 1) & 1, ak = warp >> 2;
    const int b = blockIdx.y, n0 = blockIdx.x * 64;
    const float* Ab = A + (size_t)b * Nv * Nv;
    const unsigned* HtW0 = (const unsigned*)g_Hx0T + (size_t)b * Dv * (Nv/2);
    const int aoff = AOFF(36), boff = BOFF(36);

    float acc[2][8][4];
#pragma unroll
    for (int f = 0; f < 2; f++)
#pragma unroll
        for (int j = 0; j < 8; j++)
#pragma unroll
            for (int i = 0; i < 4; i++) acc[f][j][i] = 0.f;

    for (int kt = 0; kt < Nv/64; kt++) {
        const int k0 = kt * 64;
#pragma unroll
        for (int s = 0; s < 8; s++) {      // A tile: 64 x 32 words (+ out copy)
            int i = tid + 256*s; int r = i >> 5, w = i & 31;
            float2 v = *(const float2*)&Ab[(size_t)(n0 + r)*Nv + k0 + 2*w];
            sA[r*36 + w] = pack_bf16(v.x, v.y);
            *(float2*)&outA[((size_t)b*Nv + n0 + r)*Nv + k0 + 2*w] = v;
        }
#pragma unroll
        for (int s = 0; s < 4; s++) {      // Hx0T chunk: 128 x 32 words
            int i4 = tid + 256*s; int d = i4 >> 3, c4 = (i4 & 7) << 2;
            *(uint4*)&sB[d*36 + c4] =
                *(const uint4*)&HtW0[(size_t)d*(Nv/2) + (k0 >> 1) + c4];
        }
        __syncthreads();
#pragma unroll
        for (int ks = 0; ks < 2; ks++) {
            int kw = ak*16 + ks*8;
            unsigned a0[4], a1[4], bb[4];
            ldsm4(a0, sA + (an*32     )*36 + aoff + kw);
            ldsm4(a1, sA + (an*32 + 16)*36 + aoff + kw);
#pragma unroll
            for (int p = 0; p < 4; p++) {
                ldsm4(bb, sB + (ad*64 + p*16)*36 + boff + kw);
                mma_bf16(acc[0][2*p    ], a0, bb    );
                mma_bf16(acc[0][2*p + 1], a0, bb + 2);
                mma_bf16(acc[1][2*p    ], a1, bb    );
                mma_bf16(acc[1][2*p + 1], a1, bb + 2);
            }
        }
        __syncthreads();
    }
    // reduce k-halves (warp w with w+4) via smem
    float* red = (float*)smw;
    if (ak == 1) {
        int base = (((warp - 4) * 32) + lane) * 64;
#pragma unroll
        for (int f = 0; f < 2; f++)
#pragma unroll
            for (int j = 0; j < 8; j++)
#pragma unroll
                for (int i = 0; i < 4; i++)
                    red[base + f*32 + j*4 + i] = acc[f][j][i];
    }
    __syncthreads();
    if (ak == 0) {
        int base = ((warp * 32) + lane) * 64;
        unsigned* Pb = (unsigned*)g_Hxb;
        __nv_bfloat16* Tb = g_HxT + (size_t)b * Dv * Nv;
#pragma unroll
        for (int f = 0; f < 2; f++)
#pragma unroll
            for (int j = 0; j < 8; j++) {
                float v0 = acc[f][j][0] + red[base + f*32 + j*4 + 0];
                float v1 = acc[f][j][1] + red[base + f*32 + j*4 + 1];
                float v2 = acc[f][j][2] + red[base + f*32 + j*4 + 2];
                float v3 = acc[f][j][3] + red[base + f*32 + j*4 + 3];
                int n  = an*32 + f*16 + lr;
                int cc = ad*64 + j*8 + 2*lc;
                Pb[(((size_t)b*Nv + n0+n  )*Dv + cc) >> 1] = pack_bf16(v0, v1);
                Pb[(((size_t)b*Nv + n0+n+8)*Dv + cc) >> 1] = pack_bf16(v2, v3);
                Tb[(size_t)(cc  )*Nv + n0+n  ] = __float2bfloat16(v0);
                Tb[(size_t)(cc+1)*Nv + n0+n  ] = __float2bfloat16(v1);
                Tb[(size_t)(cc  )*Nv + n0+n+8] = __float2bfloat16(v2);
                Tb[(size_t)(cc+1)*Nv + n0+n+8] = __float2bfloat16(v3);
            }
    }
}

// ---------------------------------------------------------------------------
// K3: Q[h,b] = Hx[b] @ attn[h]  (bf16 mma + ldmatrix). grid(32,B,H).
// ---------------------------------------------------------------------------
__global__ __launch_bounds__(256, 1) void q_bf16_kernel()
{
    extern __shared__ unsigned smw[];
    unsigned* sHx = smw;            // [64][WQ]   Hx tile [n][kw]
    unsigned* sAt = smw + 64*WQ;    // [128][WQ]  attnT [e][kw]
    const int tid = threadIdx.x, warp = tid >> 5, lane = tid & 31;
    const int lr = lane >> 2, lc = lane & 3;
    const int qn = warp & 1, qd = warp >> 1;     // qd 0..3
    const int b = blockIdx.y, h = blockIdx.z, n0 = blockIdx.x * 64;
    const unsigned* HbW = (const unsigned*)g_Hxb + (size_t)b * Nv * (Dv/2);
    const unsigned* ATW = (const unsigned*)g_attnT + (size_t)h * Dv * (Dv/2);
    const int aoff = AOFF(WQ), boff = BOFF(WQ);

#pragma unroll
    for (int s = 0; s < 4; s++) {       // Hx tile: 64 x 64 words
        int i4 = tid + 256*s; int r = i4 >> 4, c4 = (i4 & 15) << 2;
        *(uint4*)&sHx[r*WQ + c4] = *(const uint4*)&HbW[(size_t)(n0 + r)*(Dv/2) + c4];
    }
#pragma unroll
    for (int s = 0; s < 8; s++) {       // attnT: 128 x 64 words
        int i4 = tid + 256*s; int e = i4 >> 4, c4 = (i4 & 15) << 2;
        *(uint4*)&sAt[e*WQ + c4] = *(const uint4*)&ATW[(size_t)e*(Dv/2) + c4];
    }
    __syncthreads();

    float acc[2][4][4];
#pragma unroll
    for (int f = 0; f < 2; f++)
#pragma unroll
        for (int j = 0; j < 4; j++)
#pragma unroll
            for (int i = 0; i < 4; i++) acc[f][j][i] = 0.f;

#pragma unroll
    for (int ks = 0; ks < 8; ks++) {
        unsigned a0[4], a1[4], bb[4];
        ldsm4(a0, sHx + (qn*32     )*WQ + aoff + 8*ks);
        ldsm4(a1, sHx + (qn*32 + 16)*WQ + aoff + 8*ks);
#pragma unroll
        for (int p = 0; p < 2; p++) {
            ldsm4(bb, sAt + (qd*32 + p*16)*WQ + boff + 8*ks);
            mma_bf16(acc[0][2*p    ], a0, bb    );
            mma_bf16(acc[0][2*p + 1], a0, bb + 2);
            mma_bf16(acc[1][2*p    ], a1, bb    );
            mma_bf16(acc[1][2*p + 1], a1, bb + 2);
        }
    }
    unsigned* Ob = (unsigned*)g_Qb;
#pragma unroll
    for (int f = 0; f < 2; f++)
#pragma unroll
        for (int j = 0; j < 4; j++) {
            int n = qn*32 + f*16 + lr, cc = qd*32 + j*8 + 2*lc;
            Ob[((((size_t)h*Bv + b)*Nv + n0+n  )*Dv + cc) >> 1] =
                pack_bf16(acc[f][j][0], acc[f][j][1]);
            Ob[((((size_t)h*Bv + b)*Nv + n0+n+8)*Dv + cc) >> 1] =
                pack_bf16(acc[f][j][2], acc[f][j][3]);
        }
}

// ---------------------------------------------------------------------------
// K4: fused attention. Register-direct C (mma C-frag == next mma A-frag),
// cp.async double-buffered tiles, 2 syncs per m-tile.
// Warps (2 g1n x 4 g1m): GEMM1 32n x 16m (4 heads, C summed in f32 regs);
// GEMM2: same warp, k-range = its own 16m, acc 32n x 128d partial;
// final reduction over the 4 g1m warps.
// ---------------------------------------------------------------------------
__global__ __launch_bounds__(256, 1) void attn_bf16_kernel(const float* __restrict__ A)
{
    extern __shared__ unsigned smw[];
    unsigned* sQ = smw;                 // [4][64][WQ]

    const int tid = threadIdx.x, warp = tid >> 5, lane = tid & 31;
    const int lr = lane >> 2, lc = lane & 3;
    const int g1n = warp & 1, g1m = warp >> 1;   // g1m 0..3
    const int b = blockIdx.y, n0 = blockIdx.x * 64;
    const float* Ab = A + (size_t)b * Nv * Nv;
    const unsigned* HbW = (const unsigned*)g_Hxb + (size_t)b * Nv * (Dv/2);
    const unsigned* HtW = (const unsigned*)g_HxT + (size_t)b * Dv * (Nv/2);
    const int aoffQ = AOFF(WQ), boffQ = BOFF(WQ), boffT = BOFF(WT);

    // tile issue: sHx (64x64w), sHxT (128x32w), sAr (64x64 f32), 12 cp.async/thread
    auto issue_tile = [&](unsigned* buf, int m0) {
        unsigned* dHx  = buf;
        unsigned* dHxT = buf + 64*WQ;
        float*    dAr  = (float*)(buf + 64*WQ + 128*WT);
#pragma unroll
        for (int s = 0; s < 4; s++) {
            int i4 = tid + 256*s; int r = i4 >> 4, c4 = (i4 & 15) << 2;
            cpa16(&dHx[r*WQ + c4], &HbW[(size_t)(m0 + r)*(Dv/2) + c4]);
        }
#pragma unroll
        for (int s = 0; s < 4; s++) {
            int i4 = tid + 256*s; int d = i4 >> 3, c4 = (i4 & 7) << 2;
            cpa16(&dHxT[d*WT + c4], &HtW[(size_t)d*(Nv/2) + (m0 >> 1) + c4]);
        }
#pragma unroll
        for (int s = 0; s < 4; s++) {
            int i4 = tid + 256*s; int r = i4 >> 4, c4 = (i4 & 15) << 2;
            cpa16((unsigned*)&dAr[r*68 + c4], &Ab[(size_t)(n0 + r)*Nv + m0 + c4]);
        }
    };

    // prefetch tile 0
    issue_tile(sQ + SQ_W, 0);
    asm volatile("cp.async.commit_group;");

    // load Q (all 4 heads): 4*64*64 words (overlaps tile-0 fetch)
#pragma unroll
    for (int s = 0; s < 16; s++) {
        int i4 = tid + 256*s;
        int h = i4 >> 10, r = (i4 >> 4) & 63, c4 = (i4 & 15) * 4;
        const uint4* src = (const uint4*)((const unsigned*)g_Qb +
            (((size_t)h*Bv + b)*Nv + n0 + r) * (Dv/2));
        *(uint4*)&sQ[(h*64 + r)*WQ + c4] = src[c4 >> 2];
    }

    float acc[2][16][4];
#pragma unroll
    for (int f = 0; f < 2; f++)
#pragma unroll
        for (int j = 0; j < 16; j++)
#pragma unroll
            for (int i = 0; i < 4; i++) acc[f][j][i] = 0.f;

    for (int mt = 0; mt < Nv/64; mt++) {
        unsigned* cur = sQ + SQ_W + (mt & 1) * TILE_W;
        if (mt + 1 < Nv/64) {
            issue_tile(sQ + SQ_W + ((mt + 1) & 1) * TILE_W, (mt + 1) * 64);
            asm volatile("cp.async.commit_group;");
            asm volatile("cp.async.wait_group 1;");
        } else {
            asm volatile("cp.async.wait_group 0;");
        }
        __syncthreads();

        const unsigned* bHx  = cur;
        const unsigned* bHxT = cur + 64*WQ;
        const float*    bAr  = (const float*)(cur + 64*WQ + 128*WT);

        // hoist this warp's A values
        float aA[2][2][4];
#pragma unroll
        for (int f = 0; f < 2; f++)
#pragma unroll
            for (int jm = 0; jm < 2; jm++) {
                int n  = g1n*32 + f*16 + lr;
                int mm = g1m*16 + jm*8 + 2*lc;
                float2 a01 = *(const float2*)&bAr[ n    *68 + mm];
                float2 a23 = *(const float2*)&bAr[(n+8) *68 + mm];
                aA[f][jm][0] = a01.x; aA[f][jm][1] = a01.y;
                aA[f][jm][2] = a23.x; aA[f][jm][3] = a23.y;
            }

        // C = sum_h tanh(A * S_h), f32 registers
        float C[2][2][4];
#pragma unroll
        for (int f = 0; f < 2; f++)
#pragma unroll
            for (int jm = 0; jm < 2; jm++)
#pragma unroll
                for (int i = 0; i < 4; i++) C[f][jm][i] = 0.f;

#pragma unroll
        for (int h = 0; h < Hv; h++) {
            float s4[2][2][4];
#pragma unroll
            for (int f = 0; f < 2; f++)
#pragma unroll
                for (int jm = 0; jm < 2; jm++)
#pragma unroll
                    for (int i = 0; i < 4; i++) s4[f][jm][i] = 0.f;
            const unsigned* q = sQ + (h*64 + g1n*32)*WQ;
#pragma unroll
            for (int ks = 0; ks < 8; ks++) {
                unsigned a0[4], a1[4], bb[4];
                ldsm4(a0, q +         aoffQ + 8*ks);
                ldsm4(a1, q + 16*WQ + aoffQ + 8*ks);
                ldsm4(bb, bHx + (g1m*16)*WQ + boffQ + 8*ks);
                mma_bf16(s4[0][0], a0, bb    );
                mma_bf16(s4[0][1], a0, bb + 2);
                mma_bf16(s4[1][0], a1, bb    );
                mma_bf16(s4[1][1], a1, bb + 2);
            }
#pragma unroll
            for (int f = 0; f < 2; f++)
#pragma unroll
                for (int jm = 0; jm < 2; jm++)
#pragma unroll
                    for (int i = 0; i < 4; i++)
                        C[f][jm][i] += tanh_fast(aA[f][jm][i] * s4[f][jm][i]);
        }

        // C-fragments ARE the GEMM2 A-fragments (k = this warp's 16m)
        unsigned aC[2][4];
#pragma unroll
        for (int f = 0; f < 2; f++) {
            aC[f][0] = pack_bf16(C[f][0][0], C[f][0][1]);
            aC[f][1] = pack_bf16(C[f][0][2], C[f][0][3]);
            aC[f][2] = pack_bf16(C[f][1][0], C[f][1][1]);
            aC[f][3] = pack_bf16(C[f][1][2], C[f][1][3]);
        }

        // GEMM2: acc(32n x 128d, partial over this warp's 16m)
#pragma unroll
        for (int p = 0; p < 8; p++) {
            unsigned bb[4];
            ldsm4(bb, bHxT + (p*16)*WT + boffT + g1m*8);
            mma_bf16(acc[0][2*p    ], aC[0], bb    );
            mma_bf16(acc[0][2*p + 1], aC[0], bb + 2);
            mma_bf16(acc[1][2*p    ], aC[1], bb    );
            mma_bf16(acc[1][2*p + 1], aC[1], bb + 2);
        }
        __syncthreads();   // all reads of cur done before it is refilled
    }

    // ---- reduce over the 4 g1m warps (per g1n), then Hout
    float* red = (float*)smw;    // 6*32*128 = 24576 words, buffers dead
    if (g1m > 0) {
        int base = ((((g1m - 1)*2 + g1n) * 32) + lane) * 128;
#pragma unroll
        for (int f = 0; f < 2; f++)
#pragma unroll
            for (int j = 0; j < 16; j++)
#pragma unroll
                for (int i = 0; i < 4; i++)
                    red[base + f*64 + j*4 + i] = acc[f][j][i];
    }
    __syncthreads();
    if (g1m == 0) {
        float* Ho = g_Hout + ((size_t)b*Nv + n0)*Dv;
#pragma unroll
        for (int w = 0; w < 3; w++) {
            int base = (((w*2 + g1n) * 32) + lane) * 128;
#pragma unroll
            for (int f = 0; f < 2; f++)
#pragma unroll
                for (int j = 0; j < 16; j++)
#pragma unroll
                    for (int i = 0; i < 4; i++)
                        acc[f][j][i] += red[base + f*64 + j*4 + i];
        }
#pragma unroll
        for (int f = 0; f < 2; f++)
#pragma unroll
            for (int j = 0; j < 16; j++) {
                int n = g1n*32 + f*16 + lr;
                int d = (j >> 1)*16 + (j & 1)*8 + 2*lc;
                float v0 = fmaxf(acc[f][j][0] * 0.25f, 0.f);
                float v1 = fmaxf(acc[f][j][1] * 0.25f, 0.f);
                float v2 = fmaxf(acc[f][j][2] * 0.25f, 0.f);
                float v3 = fmaxf(acc[f][j][3] * 0.25f, 0.f);
                *(float2*)&Ho[(size_t)n    *Dv + d] = make_float2(v0, v1);
                *(float2*)&Ho[(size_t)(n+8)*Dv + d] = make_float2(v2, v3);
            }
    }
}

// ---------------------------------------------------------------------------
// K5: z = sigmoid(Hout@W_u + Xs@W_x + biases); out = Hout*z + Xs*(1-z)  (SIMT)
// ---------------------------------------------------------------------------
__global__ __launch_bounds__(256) void gate_kernel(
    const float* __restrict__ Wu, const float* __restrict__ bu,
    const float* __restrict__ Wx, const float* __restrict__ bx,
    const float* __restrict__ ub, float* __restrict__ out)
{
    extern __shared__ float sm[];
    float* sHo = sm;              // [64][132]
    float* sXs = sHo + 64*132;    // [64][132]
    float* sWu = sXs + 64*132;    // [64][128]
    float* sWx = sWu + 64*128;    // [64][128]
    const int tid = threadIdx.x, ty = tid >> 4, tx = tid & 15;
    const int row0 = blockIdx.x * 64;

#pragma unroll
    for (int s = 0; s < 8; s++) {
        int idx4 = tid + 256 * s; int r = idx4 >> 5, c4 = (idx4 & 31) * 4;
        *(float4*)&sHo[r*132 + c4] = *(const float4*)&g_Hout[(size_t)(row0 + r) * Dv + c4];
        *(float4*)&sXs[r*132 + c4] = *(const float4*)&g_Xs  [(size_t)(row0 + r) * Dv + c4];
    }

    float acc[4][8];
#pragma unroll
    for (int i = 0; i < 4; i++)
#pragma unroll
        for (int j = 0; j < 8; j++) acc[i][j] = 0.f;

    for (int k0 = 0; k0 < Dv; k0 += 64) {
#pragma unroll
        for (int s = 0; s < 8; s++) {
            int idx4 = tid + 256 * s; int r = idx4 >> 5, c4 = (idx4 & 31) * 4;
            *(float4*)&sWu[r*128 + c4] = *(const float4*)&Wu[(size_t)(k0 + r) * Dv + c4];
            *(float4*)&sWx[r*128 + c4] = *(const float4*)&Wx[(size_t)(k0 + r) * Dv + c4];
        }
        __syncthreads();
#pragma unroll 8
        for (int kk = 0; kk < 64; kk++) {
            float a1[4], a2[4], b1[8], b2[8];
#pragma unroll
            for (int i = 0; i < 4; i++) {
                a1[i] = sHo[(ty*4 + i)*132 + k0 + kk];
                a2[i] = sXs[(ty*4 + i)*132 + k0 + kk];
            }
#pragma unroll
            for (int j = 0; j < 8; j++) {
                b1[j] = sWu[kk*128 + tx + 16*j];
                b2[j] = sWx[kk*128 + tx + 16*j];
            }
#pragma unroll
            for (int i = 0; i < 4; i++)
#pragma unroll
                for (int j = 0; j < 8; j++)
                    acc[i][j] += a1[i] * b1[j] + a2[i] * b2[j];
        }
        __syncthreads();
    }
#pragma unroll
    for (int i = 0; i < 4; i++)
#pragma unroll
        for (int j = 0; j < 8; j++) {
            int r = ty*4 + i, c = tx + 16*j;
            float ho = sHo[r*132 + c];
            float xs = sXs[r*132 + c];
            float zl = acc[i][j] + bu[c] + bx[c] + ub[c];
            float z = 1.f / (1.f + expf(-zl));
            out[(size_t)(row0 + r) * Dv + c] = ho * z + xs * (1.f - z);
        }
}

// ---------------------------------------------------------------------------
extern "C" void kernel_launch(void* const* d_in, const int* in_sizes, int n_in,
                              void* d_out, int out_size)
{
    const float* X      = (const float*)d_in[0];
    const float* A      = (const float*)d_in[1];
    const float* Wk     = (const float*)d_in[2];
    const float* bias   = (const float*)d_in[3];
    const float* ub     = (const float*)d_in[4];
    const float* attn   = (const float*)d_in[5];
    const float* Wskip  = (const float*)d_in[6];
    const float* bskip  = (const float*)d_in[7];
    const float* Wu     = (const float*)d_in[8];
    const float* bu     = (const float*)d_in[9];
    const float* Wx     = (const float*)d_in[10];
    const float* bx     = (const float*)d_in[11];
    float* out = (float*)d_out;

    const int SM1 = (64*68 + 2*64*128) * 4;
    const int SM2 = 8192 * 4;
    const int SM3 = (64*WQ + 128*WQ) * 4;
    const int SM4 = (SQ_W + 2*TILE_W) * 4;          // 176,128 B
    const int SM5 = (2*64*132 + 2*64*128) * 4;
    cudaFuncSetAttribute(proj_kernel,      cudaFuncAttributeMaxDynamicSharedMemorySize, SM1);
    cudaFuncSetAttribute(aggr_bf16_kernel, cudaFuncAttributeMaxDynamicSharedMemorySize, SM2);
    cudaFuncSetAttribute(q_bf16_kernel,    cudaFuncAttributeMaxDynamicSharedMemorySize, SM3);
    cudaFuncSetAttribute(attn_bf16_kernel, cudaFuncAttributeMaxDynamicSharedMemorySize, SM4);
    cudaFuncSetAttribute(gate_kernel,      cudaFuncAttributeMaxDynamicSharedMemorySize, SM5);

    prep_attnT      <<<128, 256>>>(attn);
    proj_kernel     <<<(Bv*Nv)/64, 256, SM1>>>(X, Wk, bias, Wskip, bskip);
    aggr_bf16_kernel<<<dim3(Nv/64, Bv),     256, SM2>>>(A, out + (size_t)Bv*Nv*Dv);
    q_bf16_kernel   <<<dim3(Nv/64, Bv, Hv), 256, SM3>>>();
    attn_bf16_kernel<<<dim3(Nv/64, Bv),     256, SM4>>>(A);
    gate_kernel     <<<(Bv*Nv)/64, 256, SM5>>>(Wu, bu, Wx, bx, ub, out);
}